// round 13
// baseline (speedup 1.0000x reference)
#include <cuda_runtime.h>
#include <cuda_fp16.h>
#include <cstdint>
#include <math.h>

#define C_DIM 228
#define TOKENS 2048
#define SEQ 1024
#define HD 57
#define LANES 4
#define FF 912
#define NLAYER 4
#define VOCAB 50257
#define VPAD 50304
#define KPAD 256
#define WKP 240
#define WNP 256

// ------------------------------------------------------------------
// Scratch
// ------------------------------------------------------------------
__device__ float g_x   [TOKENS * C_DIM];
__device__ float g_v   [TOKENS * C_DIM];
__device__ float g_bufA[TOKENS * C_DIM];
__device__ float g_bufB[TOKENS * C_DIM];
__device__ float g_mlp [TOKENS * FF];
__device__ float2 g_stats[TOKENS];
__device__ __half g_wte_h[VPAD * KPAD];
__device__ __half g_x_h  [TOKENS * KPAD];
__device__ __half g_wsh  [NLAYER * WNP * WKP];
__device__ __half g_wsl  [NLAYER * WNP * WKP];
__device__ unsigned g_bar_cnt = 0;
__device__ unsigned g_bar_gen = 0;

__device__ __forceinline__ float gelu_f(float x) {
    float x3 = x * x * x;
    return 0.5f * x * (1.0f + tanhf(0.7978845608028654f * (x + 0.044715f * x3)));
}
__device__ __forceinline__ void mma16(float* c, const uint32_t* a, const uint32_t* b) {
    asm volatile("mma.sync.aligned.m16n8k16.row.col.f32.f16.f16.f32 "
        "{%0,%1,%2,%3}, {%4,%5,%6,%7}, {%8,%9}, {%0,%1,%2,%3};"
        : "+f"(c[0]), "+f"(c[1]), "+f"(c[2]), "+f"(c[3])
        : "r"(a[0]), "r"(a[1]), "r"(a[2]), "r"(a[3]), "r"(b[0]), "r"(b[1]));
}
__device__ __forceinline__ uint32_t pack_h2(float x, float y) {
    __half2 h = __halves2half2(__float2half_rn(x), __float2half_rn(y));
    return *(uint32_t*)&h;
}
__device__ __forceinline__ void split_h2(float x, float y, uint32_t& hi, uint32_t& lo) {
    __half hx = __float2half_rn(x), hy = __float2half_rn(y);
    float rx = x - __half2float(hx), ry = y - __half2float(hy);
    __half2 h = __halves2half2(hx, hy);
    __half2 l = __halves2half2(__float2half_rn(rx), __float2half_rn(ry));
    hi = *(uint32_t*)&h;
    lo = *(uint32_t*)&l;
}
__device__ __forceinline__ uint32_t smem_u32(const void* p) {
    uint32_t a;
    asm("{ .reg .u64 t; cvta.to.shared.u64 t, %1; cvt.u32.u64 %0, t; }" : "=r"(a) : "l"(p));
    return a;
}
__device__ __forceinline__ void cp_async16(uint32_t dst, const void* src) {
    asm volatile("cp.async.cg.shared.global [%0], [%1], 16;" :: "r"(dst), "l"(src));
}

// ------------------------------------------------------------------
// Embedding gather (int32/int64 auto-detect)
// ------------------------------------------------------------------
__global__ __launch_bounds__(256) void embed_kernel(const int* __restrict__ idx32,
                                                    const float* __restrict__ wte,
                                                    float* __restrict__ x) {
    __shared__ int s_is64;
    if (threadIdx.x == 0) {
        int all0 = 1;
        #pragma unroll
        for (int i = 1; i < 16; i += 2)
            if (idx32[i] != 0) all0 = 0;
        s_is64 = all0;
    }
    __syncthreads();
    int gid = blockIdx.x * 256 + threadIdx.x;
    if (gid >= TOKENS * C_DIM) return;
    int t = gid / C_DIM;
    int c = gid - t * C_DIM;
    int id = s_is64 ? idx32[2 * t] : idx32[t];
    x[gid] = wte[id * C_DIM + c];
}

// ------------------------------------------------------------------
// f32 -> padded f16 conversion (wte / final x)
// ------------------------------------------------------------------
__global__ __launch_bounds__(256) void cvt_half_kernel(const float* __restrict__ src,
                                                       __half* __restrict__ dst,
                                                       int dstRows, int srcRows) {
    int idx = blockIdx.x * 256 + threadIdx.x;
    if (idx >= dstRows * 64) return;
    int r = idx >> 6, c4 = idx & 63;
    uint32_t p[2];
    if (c4 < 57 && r < srcRows) {
        float4 v = *(const float4*)&src[r * C_DIM + c4 * 4];
        p[0] = pack_h2(v.x, v.y);
        p[1] = pack_h2(v.z, v.w);
    } else {
        p[0] = 0u; p[1] = 0u;
    }
    *(uint2*)&dst[r * KPAD + c4 * 4] = *(uint2*)p;
}

// ------------------------------------------------------------------
// w_scan (all layers) -> transposed fp16 hi + lo, zero-padded.
// ------------------------------------------------------------------
__global__ __launch_bounds__(256) void cvt_wscan_kernel(const float* __restrict__ wsc,
                                                        __half* __restrict__ WhT,
                                                        __half* __restrict__ WlT) {
    int idx = blockIdx.x * 256 + threadIdx.x;
    if (idx >= NLAYER * WKP * 57) return;
    int L = idx / (WKP * 57);
    int rem = idx - L * (WKP * 57);
    int k = rem / 57, n4 = rem - (rem / 57) * 57;
    float4 v = make_float4(0.f, 0.f, 0.f, 0.f);
    if (k < C_DIM)
        v = *(const float4*)&wsc[L * C_DIM * C_DIM + k * C_DIM + n4 * 4];
    __half* wh = WhT + L * WNP * WKP;
    __half* wl = WlT + L * WNP * WKP;
    const float* vv = (const float*)&v;
    #pragma unroll
    for (int j = 0; j < 4; j++) {
        float x = vv[j];
        __half hi = __float2half_rn(x);
        __half lo = __float2half_rn(x - __half2float(hi));
        wh[(n4 * 4 + j) * WKP + k] = hi;
        wl[(n4 * 4 + j) * WKP + k] = lo;
    }
}

// ------------------------------------------------------------------
// LN stats only (float4 reads): mean + rstd per token
// ------------------------------------------------------------------
__global__ __launch_bounds__(256) void ln_stats_kernel(const float* __restrict__ x,
                                                       float2* __restrict__ stats) {
    int w = (blockIdx.x * 256 + threadIdx.x) >> 5;
    int lane = threadIdx.x & 31;
    if (w >= TOKENS) return;
    const float* row = x + w * C_DIM;
    float s = 0.f, s2 = 0.f;
    for (int c4 = lane; c4 < 57; c4 += 32) {
        float4 v = *(const float4*)&row[c4 * 4];
        s  += v.x + v.y + v.z + v.w;
        s2 += v.x * v.x + v.y * v.y + v.z * v.z + v.w * v.w;
    }
    #pragma unroll
    for (int o = 16; o > 0; o >>= 1) {
        s  += __shfl_xor_sync(0xffffffffu, s, o);
        s2 += __shfl_xor_sync(0xffffffffu, s2, o);
    }
    if (lane == 0) {
        float mean = s * (1.0f / C_DIM);
        float var = s2 * (1.0f / C_DIM) - mean * mean;
        stats[w] = make_float2(mean, rsqrtf(var + 1e-5f));
    }
}

// ------------------------------------------------------------------
// Split-fp16 internal GEMM (NT). AMODE 0 plain / 1 LN-fused / 2 A*A2.
// EPI 0 store / 1 += / 2 gelu.   (R11-proven)
// ------------------------------------------------------------------
template<int AMODE, int EPI>
__global__ __launch_bounds__(256) void hgemm(
    const float* __restrict__ A, const float* __restrict__ A2,
    const float* __restrict__ B, float* __restrict__ Cc,
    int M, int N, int K,
    const float2* __restrict__ stats, const float* __restrict__ gamma)
{
    __shared__ uint32_t Ah[64][20], Al[64][20], Bh[64][20], Bl[64][20];
    const int tid = threadIdx.x;
    const int lane = tid & 31, wid = tid >> 5;
    const int wm = wid >> 2, wn = wid & 3;
    const int l3 = lane & 3, lq = lane >> 2;
    const int m0 = blockIdx.x * 64, n0 = blockIdx.y * 64;

    float acc[2][2][4];
    #pragma unroll
    for (int i = 0; i < 2; i++)
        #pragma unroll
        for (int j = 0; j < 2; j++)
            #pragma unroll
            for (int q = 0; q < 4; q++) acc[i][j][q] = 0.f;

    const int nchunk = (K + 31) / 32;

    auto loadA = [&](int r, int k) -> float4 {
        float4 v = make_float4(0.f,0.f,0.f,0.f);
        if (k + 3 < K) {
            v = *(const float4*)&A[(m0 + r) * K + k];
            if (AMODE == 1) {
                float2 st = stats[m0 + r];
                float4 gg = *(const float4*)&gamma[k];
                v.x = (v.x - st.x) * st.y * gg.x;
                v.y = (v.y - st.x) * st.y * gg.y;
                v.z = (v.z - st.x) * st.y * gg.z;
                v.w = (v.w - st.x) * st.y * gg.w;
            }
            if (AMODE == 2) {
                float4 u = *(const float4*)&A2[(m0 + r) * K + k];
                v.x *= u.x; v.y *= u.y; v.z *= u.z; v.w *= u.w;
            }
        }
        return v;
    };

    float4 pa[2], pb[2];
    #pragma unroll
    for (int i = 0; i < 2; i++) {
        int idx = tid + i * 256;
        int r = idx >> 3, f = idx & 7;
        int k = f * 4;
        pa[i] = loadA(r, k);
        float4 v = make_float4(0.f,0.f,0.f,0.f);
        if (k + 3 < K && (n0 + r) < N)
            v = *(const float4*)&B[(n0 + r) * K + k];
        pb[i] = v;
    }

    for (int ch = 0; ch < nchunk; ch++) {
        __syncthreads();
        #pragma unroll
        for (int i = 0; i < 2; i++) {
            int idx = tid + i * 256;
            int r = idx >> 3, f = idx & 7;
            uint32_t h0, l0, h1, l1;
            split_h2(pa[i].x, pa[i].y, h0, l0);
            split_h2(pa[i].z, pa[i].w, h1, l1);
            Ah[r][f*2] = h0; Ah[r][f*2+1] = h1;
            Al[r][f*2] = l0; Al[r][f*2+1] = l1;
            split_h2(pb[i].x, pb[i].y, h0, l0);
            split_h2(pb[i].z, pb[i].w, h1, l1);
            Bh[r][f*2] = h0; Bh[r][f*2+1] = h1;
            Bl[r][f*2] = l0; Bl[r][f*2+1] = l1;
        }
        __syncthreads();
        if (ch + 1 < nchunk) {
            int k0 = (ch + 1) * 32;
            #pragma unroll
            for (int i = 0; i < 2; i++) {
                int idx = tid + i * 256;
                int r = idx >> 3, f = idx & 7;
                int k = k0 + f * 4;
                pa[i] = loadA(r, k);
                float4 v = make_float4(0.f,0.f,0.f,0.f);
                if (k + 3 < K && (n0 + r) < N)
                    v = *(const float4*)&B[(n0 + r) * K + k];
                pb[i] = v;
            }
        }
        #pragma unroll
        for (int kc2 = 0; kc2 < 16; kc2 += 8) {
            uint32_t ah[2][4], al[2][4], bh[2][2], bl[2][2];
            #pragma unroll
            for (int mt = 0; mt < 2; mt++) {
                int r = wm * 32 + mt * 16 + lq;
                ah[mt][0] = Ah[r    ][kc2 + l3];
                ah[mt][1] = Ah[r + 8][kc2 + l3];
                ah[mt][2] = Ah[r    ][kc2 + 4 + l3];
                ah[mt][3] = Ah[r + 8][kc2 + 4 + l3];
                al[mt][0] = Al[r    ][kc2 + l3];
                al[mt][1] = Al[r + 8][kc2 + l3];
                al[mt][2] = Al[r    ][kc2 + 4 + l3];
                al[mt][3] = Al[r + 8][kc2 + 4 + l3];
            }
            #pragma unroll
            for (int nt = 0; nt < 2; nt++) {
                int n = wn * 16 + nt * 8 + lq;
                bh[nt][0] = Bh[n][kc2 + l3];
                bh[nt][1] = Bh[n][kc2 + 4 + l3];
                bl[nt][0] = Bl[n][kc2 + l3];
                bl[nt][1] = Bl[n][kc2 + 4 + l3];
            }
            #pragma unroll
            for (int mt = 0; mt < 2; mt++)
                #pragma unroll
                for (int nt = 0; nt < 2; nt++) {
                    mma16(acc[mt][nt], ah[mt], bh[nt]);
                    mma16(acc[mt][nt], ah[mt], bl[nt]);
                    mma16(acc[mt][nt], al[mt], bh[nt]);
                }
        }
    }

    #pragma unroll
    for (int mt = 0; mt < 2; mt++) {
        #pragma unroll
        for (int nt = 0; nt < 2; nt++) {
            int n = n0 + wn * 16 + nt * 8 + l3 * 2;
            #pragma unroll
            for (int half = 0; half < 2; half++) {
                int mm = m0 + wm * 32 + mt * 16 + lq + half * 8;
                float r0 = acc[mt][nt][half * 2];
                float r1 = acc[mt][nt][half * 2 + 1];
                if (n < N) {
                    if (EPI == 1) r0 += Cc[mm * N + n];
                    if (EPI == 2) r0 = gelu_f(r0);
                    Cc[mm * N + n] = r0;
                }
                if (n + 1 < N) {
                    if (EPI == 1) r1 += Cc[mm * N + n + 1];
                    if (EPI == 2) r1 = gelu_f(r1);
                    Cc[mm * N + n + 1] = r1;
                }
            }
        }
    }
}

// ------------------------------------------------------------------
// Pipelined fp16 lm_head — R8-proven.
// ------------------------------------------------------------------
#define LMH_AW   (128 * 36)
#define LMH_SW   (2 * LMH_AW)
#define LMH_SMEM (2 * LMH_SW * 4)

__global__ __launch_bounds__(256) void lmhead_h2(
    const __half* __restrict__ Ah_g, const __half* __restrict__ Bh_g,
    float* __restrict__ C)
{
    extern __shared__ uint32_t dsm[];
    const uint32_t smem_base = smem_u32(dsm);

    const int tid = threadIdx.x;
    const int lane = tid & 31, wid = tid >> 5;
    const int wm = wid >> 2, wn = wid & 3;
    const int l3 = lane & 3, lq = lane >> 2;
    const int m0 = blockIdx.x * 128, n0 = blockIdx.y * 128;

    float acc[4][4][4];
    #pragma unroll
    for (int i = 0; i < 4; i++)
        #pragma unroll
        for (int j = 0; j < 4; j++)
            #pragma unroll
            for (int q = 0; q < 4; q++) acc[i][j][q] = 0.f;

    const int r_ld = tid >> 3;
    const int c16  = tid & 7;

    auto issue = [&](int kc, int bi) {
        uint32_t ab = smem_base + (uint32_t)bi * (LMH_SW * 4);
        uint32_t bb = ab + LMH_AW * 4;
        const __half* asrc = Ah_g + (size_t)(m0 + r_ld) * KPAD + kc * 64 + c16 * 8;
        const __half* bsrc = Bh_g + (size_t)(n0 + r_ld) * KPAD + kc * 64 + c16 * 8;
        #pragma unroll
        for (int i = 0; i < 4; i++) {
            int r = r_ld + i * 32;
            cp_async16(ab + (uint32_t)(r * 36 + c16 * 4) * 4,
                       asrc + (size_t)(i * 32) * KPAD);
            cp_async16(bb + (uint32_t)(r * 36 + c16 * 4) * 4,
                       bsrc + (size_t)(i * 32) * KPAD);
        }
        asm volatile("cp.async.commit_group;" ::: "memory");
    };

    issue(0, 0);

    #pragma unroll 1
    for (int kc = 0; kc < 4; kc++) {
        if (kc + 1 < 4) {
            issue(kc + 1, (kc + 1) & 1);
            asm volatile("cp.async.wait_group 1;" ::: "memory");
        } else {
            asm volatile("cp.async.wait_group 0;" ::: "memory");
        }
        __syncthreads();

        const uint32_t* As2 = dsm + (kc & 1) * LMH_SW;
        const uint32_t* Bs2 = As2 + LMH_AW;

        #pragma unroll
        for (int kc2 = 0; kc2 < 32; kc2 += 8) {
            uint32_t af[4][4], bf[4][2];
            #pragma unroll
            for (int mt = 0; mt < 4; mt++) {
                int r = wm * 64 + mt * 16 + lq;
                af[mt][0] = As2[r * 36 + kc2 + l3];
                af[mt][1] = As2[(r + 8) * 36 + kc2 + l3];
                af[mt][2] = As2[r * 36 + kc2 + 4 + l3];
                af[mt][3] = As2[(r + 8) * 36 + kc2 + 4 + l3];
            }
            #pragma unroll
            for (int nt = 0; nt < 4; nt++) {
                int n = wn * 32 + nt * 8 + lq;
                bf[nt][0] = Bs2[n * 36 + kc2 + l3];
                bf[nt][1] = Bs2[n * 36 + kc2 + 4 + l3];
            }
            #pragma unroll
            for (int mt = 0; mt < 4; mt++)
                #pragma unroll
                for (int nt = 0; nt < 4; nt++)
                    mma16(acc[mt][nt], af[mt], bf[nt]);
        }
        __syncthreads();
    }

    #pragma unroll
    for (int mt = 0; mt < 4; mt++) {
        #pragma unroll
        for (int nt = 0; nt < 4; nt++) {
            int n = n0 + wn * 32 + nt * 8 + l3 * 2;
            #pragma unroll
            for (int half = 0; half < 2; half++) {
                int mm = m0 + wm * 64 + mt * 16 + lq + half * 8;
                float* dst = &C[(size_t)mm * VOCAB + n];
                if (n     < VOCAB) dst[0] = acc[mt][nt][half * 2];
                if (n + 1 < VOCAB) dst[1] = acc[mt][nt][half * 2 + 1];
            }
        }
    }
}

// ------------------------------------------------------------------
// Grid-wide barrier (all 128 blocks resident)
// ------------------------------------------------------------------
__device__ __forceinline__ void grid_barrier() {
    __syncthreads();
    if (threadIdx.x == 0) {
        __threadfence();
        unsigned gen = atomicAdd(&g_bar_gen, 0u);
        unsigned t = atomicAdd(&g_bar_cnt, 1u);
        if (t == gridDim.x - 1) {
            atomicExch(&g_bar_cnt, 0u);
            __threadfence();
            atomicAdd(&g_bar_gen, 1u);
        } else {
            while (atomicAdd(&g_bar_gen, 0u) == gen) __nanosleep(64);
        }
    }
    __syncthreads();
}

// ------------------------------------------------------------------
// Persistent pscan v4: Wh RESIDENT (232 rows), Wl restaged per step
// (two 128-row chunks, chunk0 overlapped behind the hi-MMA loop).
// Full 3-term accuracy: ah*bh + al*bh + ah*bl.
// 128 blocks x 512 threads, 16 tokens/block.
// smem words: mAh 16*124, mAl 16*124, rr 16*232, mx 16*232,
//             Wh 232*124, Wl 128*124  -> 224128 B
// ------------------------------------------------------------------
#define SCW_AW (16 * 124)
#define SCW_RR (16 * 232)
#define SCW_MX (16 * 232)
#define SCW_WH (232 * 124)
#define SCW_WL (128 * 124)
#define SCW_SMEM ((2*SCW_AW + SCW_RR + SCW_MX + SCW_WH + SCW_WL) * 4)

__global__ __launch_bounds__(512) void scan_all_h(
    float* __restrict__ x0, float* __restrict__ x1,
    const __half* __restrict__ WhT, const __half* __restrict__ WlT,
    const float* __restrict__ ident)
{
    extern __shared__ uint32_t su[];
    uint32_t* mAh = su;
    uint32_t* mAl = mAh + SCW_AW;
    float*    rr  = (float*)(mAl + SCW_AW);
    float*    mx  = rr + SCW_RR;
    uint32_t* Wh  = (uint32_t*)(mx + SCW_MX);
    uint32_t* Wl  = Wh + SCW_WH;
    const uint32_t wh_base = smem_u32(Wh);
    const uint32_t wl_base = smem_u32(Wl);
    __half* mAh_h = (__half*)mAh;
    __half* mAl_h = (__half*)mAl;

    const int tid = threadIdx.x;
    const int lane = tid & 31, wid = tid >> 5;   // wid 0..15
    const int l3 = lane & 3, lq = lane >> 2;
    const int T0 = blockIdx.x * 16;
    const int half_id = tid >> 8;
    const int hc = tid & 255;

    // ---- stage Wh (rows 0..231) ONCE, resident for all steps ----
    for (int i = tid; i < 232 * 30; i += 512) {
        int n = i / 30, s5 = i - (i / 30) * 30;
        cp_async16(wh_base + (uint32_t)(n * 124 + s5 * 4) * 4,
                   WhT + (size_t)n * WKP + s5 * 8);
    }
    asm volatile("cp.async.commit_group;" ::: "memory");
    asm volatile("cp.async.wait_group 0;" ::: "memory");
    __syncthreads();

    int step = 0;
    for (int off = 1; off < SEQ; off <<= 1, step++) {
        const float* xin = (step & 1) ? x1 : x0;
        float* xout      = (step & 1) ? x0 : x1;

        // ---- issue Wl chunk0 (rows 0..127); lands during hi-MMA loop ----
        for (int i = tid; i < 128 * 30; i += 512) {
            int n = i / 30, s5 = i - (i / 30) * 30;
            cp_async16(wl_base + (uint32_t)(n * 124 + s5 * 4) * 4,
                       WlT + (size_t)n * WKP + s5 * 8);
        }
        asm volatile("cp.async.commit_group;" ::: "memory");

        // ---- load + fp16 hi/lo split ----
        if (hc < 248) {
            int c = hc;
            #pragma unroll
            for (int tl = 0; tl < 8; tl++) {
                int t = half_id * 8 + tl;
                int tok = T0 + t;
                int tt = tok & (SEQ - 1);
                float rv = 0.f, lv = 0.f;
                if (c < C_DIM) {
                    rv = xin[tok * C_DIM + c];
                    lv = (tt >= off) ? xin[(tok - off) * C_DIM + c] : ident[c];
                }
                if (c < 232) rr[t * 232 + c] = rv;
                float s = lv + rv;
                __half hi = __float2half_rn(s);
                __half lo = __float2half_rn(s - __half2float(hi));
                mAh_h[t * 248 + c] = hi;
                mAl_h[t * 248 + c] = lo;
            }
        }
        __syncthreads();

        // ---- hi-MMA loop (Wh resident) ----
        float acc[2][4];
        #pragma unroll
        for (int i = 0; i < 2; i++)
            #pragma unroll
            for (int q = 0; q < 4; q++) acc[i][q] = 0.f;

        const bool ci1_ok = (wid < 13);   // n = 128+wid*8+lq < 232
        #pragma unroll
        for (int kk = 0; kk < 15; kk++) {
            uint32_t ah[4], al[4], bh[2];
            ah[0] = mAh[lq * 124 + kk * 8 + l3];
            ah[1] = mAh[(lq + 8) * 124 + kk * 8 + l3];
            ah[2] = mAh[lq * 124 + kk * 8 + 4 + l3];
            ah[3] = mAh[(lq + 8) * 124 + kk * 8 + 4 + l3];
            al[0] = mAl[lq * 124 + kk * 8 + l3];
            al[1] = mAl[(lq + 8) * 124 + kk * 8 + l3];
            al[2] = mAl[lq * 124 + kk * 8 + 4 + l3];
            al[3] = mAl[(lq + 8) * 124 + kk * 8 + 4 + l3];
            {
                int n = wid * 8 + lq;
                bh[0] = Wh[n * 124 + kk * 8 + l3];
                bh[1] = Wh[n * 124 + kk * 8 + 4 + l3];
                mma16(acc[0], ah, bh);
                mma16(acc[0], al, bh);
            }
            if (ci1_ok) {
                int n = 128 + wid * 8 + lq;
                bh[0] = Wh[n * 124 + kk * 8 + l3];
                bh[1] = Wh[n * 124 + kk * 8 + 4 + l3];
                mma16(acc[1], ah, bh);
                mma16(acc[1], al, bh);
            }
        }

        // ---- Wl chunk0 ready: lo-MMAs for ci=0 ----
        asm volatile("cp.async.wait_group 0;" ::: "memory");
        __syncthreads();
        #pragma unroll
        for (int kk = 0; kk < 15; kk++) {
            uint32_t ah[4], bl[2];
            ah[0] = mAh[lq * 124 + kk * 8 + l3];
            ah[1] = mAh[(lq + 8) * 124 + kk * 8 + l3];
            ah[2] = mAh[lq * 124 + kk * 8 + 4 + l3];
            ah[3] = mAh[(lq + 8) * 124 + kk * 8 + 4 + l3];
            int n = wid * 8 + lq;
            bl[0] = Wl[n * 124 + kk * 8 + l3];
            bl[1] = Wl[n * 124 + kk * 8 + 4 + l3];
            mma16(acc[0], ah, bl);
        }
        __syncthreads();

        // ---- stage Wl chunk1 (rows 128..255), then lo-MMAs for ci=1 ----
        for (int i = tid; i < 128 * 30; i += 512) {
            int n = i / 30, s5 = i - (i / 30) * 30;
            cp_async16(wl_base + (uint32_t)(n * 124 + s5 * 4) * 4,
                       WlT + (size_t)(128 + n) * WKP + s5 * 8);
        }
        asm volatile("cp.async.commit_group;" ::: "memory");
        asm volatile("cp.async.wait_group 0;" ::: "memory");
        __syncthreads();
        if (ci1_ok) {
            #pragma unroll
            for (int kk = 0; kk < 15; kk++) {
                uint32_t ah[4], bl[2];
                ah[0] = mAh[lq * 124 + kk * 8 + l3];
                ah[1] = mAh[(lq + 8) * 124 + kk * 8 + l3];
                ah[2] = mAh[lq * 124 + kk * 8 + 4 + l3];
                ah[3] = mAh[(lq + 8) * 124 + kk * 8 + 4 + l3];
                int n = wid * 8 + lq;
                bl[0] = Wl[n * 124 + kk * 8 + l3];
                bl[1] = Wl[n * 124 + kk * 8 + 4 + l3];
                mma16(acc[1], ah, bl);
            }
        }

        // ---- store mix ----
        #pragma unroll
        for (int ci = 0; ci < 2; ci++) {
            int n = ci * 128 + wid * 8 + l3 * 2;
            if (n < C_DIM) {
                mx[lq * 232 + n]       = acc[ci][0];
                mx[(lq + 8) * 232 + n] = acc[ci][2];
            }
            if (n + 1 < C_DIM) {
                mx[lq * 232 + n + 1]       = acc[ci][1];
                mx[(lq + 8) * 232 + n + 1] = acc[ci][3];
            }
        }
        __syncthreads();

        // ---- combine: 64 (token,lane) pairs, 4 per warp ----
        const int d0 = lane;
        const int d1 = lane + 32;
        const bool has1 = (lane < HD - 32);
        #pragma unroll
        for (int e = 0; e < 4; e++) {
            int p = wid * 4 + e;
            int t = p >> 2;
            int l = p & 3;
            int tok = T0 + t;

            float s0 = __half2float(mAh_h[t * 248 + l * HD + d0])
                     + __half2float(mAl_h[t * 248 + l * HD + d0]);
            float q0 = s0 - rr[t * 232 + l * HD + d0];
            float q1 = 0.f;
            if (has1) {
                float s1 = __half2float(mAh_h[t * 248 + l * HD + d1])
                         + __half2float(mAl_h[t * 248 + l * HD + d1]);
                q1 = s1 - rr[t * 232 + l * HD + d1];
            }

            float sc[4];
            #pragma unroll
            for (int m = 0; m < 4; m++) {
                float pr = q0 * rr[t * 232 + m * HD + d0];
                if (has1) pr += q1 * rr[t * 232 + m * HD + d1];
                #pragma unroll
                for (int o = 16; o > 0; o >>= 1) pr += __shfl_xor_sync(0xffffffffu, pr, o);
                sc[m] = pr * 0.13245323570650439f;
            }
            float mxv = fmaxf(fmaxf(sc[0], sc[1]), fmaxf(sc[2], sc[3]));
            float e0 = expf(sc[0] - mxv), e1 = expf(sc[1] - mxv);
            float e2 = expf(sc[2] - mxv), e3 = expf(sc[3] - mxv);
            float inv = 1.0f / (e0 + e1 + e2 + e3);
            float a0 = e0 * inv, a1 = e1 * inv, a2 = e2 * inv, a3 = e3 * inv;

            float z0 = a0 * mx[t * 232 + 0 * HD + d0] + a1 * mx[t * 232 + 1 * HD + d0]
                     + a2 * mx[t * 232 + 2 * HD + d0] + a3 * mx[t * 232 + 3 * HD + d0];
            float z1 = 0.f;
            if (has1)
                z1 = a0 * mx[t * 232 + 0 * HD + d1] + a1 * mx[t * 232 + 1 * HD + d1]
                   + a2 * mx[t * 232 + 2 * HD + d1] + a3 * mx[t * 232 + 3 * HD + d1];

            float ss = z0 * z0 + z1 * z1;
            #pragma unroll
            for (int o = 16; o > 0; o >>= 1) ss += __shfl_xor_sync(0xffffffffu, ss, o);
            float scale = rsqrtf(ss * (1.0f / 57.0f) + 1e-6f) / (1.0f + (float)l);

            xout[tok * C_DIM + l * HD + d0] = q0 + z0 * scale;
            if (has1) xout[tok * C_DIM + l * HD + d1] = q1 + z1 * scale;
        }

        if ((off << 1) < SEQ) grid_barrier();
    }
}

// ------------------------------------------------------------------
extern "C" void kernel_launch(void* const* d_in, const int* in_sizes, int n_in,
                              void* d_out, int out_size) {
    const int*   idx    = (const int*)  d_in[0];
    const float* wte    = (const float*)d_in[1];
    const float* ln1_g  = (const float*)d_in[2];
    const float* ln2_g  = (const float*)d_in[3];
    const float* w_up   = (const float*)d_in[4];
    const float* w_v    = (const float*)d_in[5];
    const float* w_cpr  = (const float*)d_in[6];
    const float* w_scan = (const float*)d_in[7];
    const float* ident  = (const float*)d_in[8];
    const float* w_fc   = (const float*)d_in[9];
    const float* w_proj = (const float*)d_in[10];
    float* out = (float*)d_out;

    float *px, *pv, *pa, *pb, *pmlp;
    float2* pst;
    __half *pwh, *pxh, *pwsh, *pwsl;
    cudaGetSymbolAddress((void**)&px,   g_x);
    cudaGetSymbolAddress((void**)&pv,   g_v);
    cudaGetSymbolAddress((void**)&pa,   g_bufA);
    cudaGetSymbolAddress((void**)&pb,   g_bufB);
    cudaGetSymbolAddress((void**)&pmlp, g_mlp);
    cudaGetSymbolAddress((void**)&pst,  g_stats);
    cudaGetSymbolAddress((void**)&pwh,  g_wte_h);
    cudaGetSymbolAddress((void**)&pxh,  g_x_h);
    cudaGetSymbolAddress((void**)&pwsh, g_wsh);
    cudaGetSymbolAddress((void**)&pwsl, g_wsl);

    cudaFuncSetAttribute(scan_all_h,
                         cudaFuncAttributeMaxDynamicSharedMemorySize, SCW_SMEM);
    cudaFuncSetAttribute(lmhead_h2,
                         cudaFuncAttributeMaxDynamicSharedMemorySize, LMH_SMEM);

    const int CC = C_DIM * C_DIM;
    const int FC = FF * C_DIM;

    embed_kernel<<<(TOKENS * C_DIM + 255) / 256, 256>>>(idx, wte, px);
    cvt_half_kernel<<<(VPAD * 64 + 255) / 256, 256>>>(wte, pwh, VPAD, VOCAB);
    cvt_wscan_kernel<<<(NLAYER * WKP * 57 + 255) / 256, 256>>>(w_scan, pwsh, pwsl);

    for (int L = 0; L < NLAYER; L++) {
        const float* wupL  = w_up   + L * CC;
        const float* wvL   = w_v    + L * CC;
        const float* wcprL = w_cpr  + L * CC;
        const float* idL   = ident  + L * C_DIM;
        const float* wfcL  = w_fc   + L * FC;
        const float* wprL  = w_proj + L * FC;

        ln_stats_kernel<<<(TOKENS * 32 + 255) / 256, 256>>>(px, pst);

        dim3 gs(TOKENS / 64, (C_DIM + 63) / 64);
        hgemm<1,0><<<gs, 256>>>(px, nullptr, wupL, pa, TOKENS, C_DIM, C_DIM,
                                pst, ln1_g + L * C_DIM);
        hgemm<1,0><<<gs, 256>>>(px, nullptr, wvL,  pv, TOKENS, C_DIM, C_DIM,
                                pst, ln1_g + L * C_DIM);

        scan_all_h<<<TOKENS / 16, 512, SCW_SMEM>>>(
            pa, pb, pwsh + (size_t)L * WNP * WKP, pwsl + (size_t)L * WNP * WKP, idL);

        hgemm<2,1><<<gs, 256>>>(pa, pv, wcprL, px, TOKENS, C_DIM, C_DIM,
                                nullptr, nullptr);

        ln_stats_kernel<<<(TOKENS * 32 + 255) / 256, 256>>>(px, pst);

        dim3 gf(TOKENS / 64, (FF + 63) / 64);
        hgemm<1,2><<<gf, 256>>>(px, nullptr, wfcL, pmlp, TOKENS, FF, C_DIM,
                                pst, ln2_g + L * C_DIM);
        hgemm<0,1><<<gs, 256>>>(pmlp, nullptr, wprL, px, TOKENS, C_DIM, FF,
                                nullptr, nullptr);
    }

    cvt_half_kernel<<<(TOKENS * 64 + 255) / 256, 256>>>(px, pxh, TOKENS, TOKENS);

    dim3 gl(TOKENS / 128, VPAD / 128);
    lmhead_h2<<<gl, 256, LMH_SMEM>>>(pxh, pwh, out);
}

// round 14
// speedup vs baseline: 1.0568x; 1.0568x over previous
#include <cuda_runtime.h>
#include <cuda_fp16.h>
#include <cstdint>
#include <math.h>

#define C_DIM 228
#define TOKENS 2048
#define SEQ 1024
#define HD 57
#define LANES 4
#define FF 912
#define NLAYER 4
#define VOCAB 50257
#define VPAD 50304
#define KPAD 256
#define WKP 240
#define WNP 256

// ------------------------------------------------------------------
// Scratch
// ------------------------------------------------------------------
__device__ float g_x   [TOKENS * C_DIM];
__device__ float g_v   [TOKENS * C_DIM];
__device__ float g_bufA[TOKENS * C_DIM];
__device__ float g_bufB[TOKENS * C_DIM];
__device__ float g_mlp [TOKENS * FF];
__device__ float2 g_stats[TOKENS];
__device__ __half g_wte_h[VPAD * KPAD];
__device__ __half g_x_h  [TOKENS * KPAD];
__device__ __half g_wsh  [NLAYER * WNP * WKP];
__device__ __half g_wsl  [NLAYER * WNP * WKP];
__device__ unsigned g_bar_cnt = 0;
__device__ unsigned g_bar_gen = 0;

__device__ __forceinline__ float gelu_f(float x) {
    float x3 = x * x * x;
    return 0.5f * x * (1.0f + tanhf(0.7978845608028654f * (x + 0.044715f * x3)));
}
__device__ __forceinline__ void mma16(float* c, const uint32_t* a, const uint32_t* b) {
    asm volatile("mma.sync.aligned.m16n8k16.row.col.f32.f16.f16.f32 "
        "{%0,%1,%2,%3}, {%4,%5,%6,%7}, {%8,%9}, {%0,%1,%2,%3};"
        : "+f"(c[0]), "+f"(c[1]), "+f"(c[2]), "+f"(c[3])
        : "r"(a[0]), "r"(a[1]), "r"(a[2]), "r"(a[3]), "r"(b[0]), "r"(b[1]));
}
__device__ __forceinline__ uint32_t pack_h2(float x, float y) {
    __half2 h = __halves2half2(__float2half_rn(x), __float2half_rn(y));
    return *(uint32_t*)&h;
}
__device__ __forceinline__ void split_h2(float x, float y, uint32_t& hi, uint32_t& lo) {
    __half hx = __float2half_rn(x), hy = __float2half_rn(y);
    float rx = x - __half2float(hx), ry = y - __half2float(hy);
    __half2 h = __halves2half2(hx, hy);
    __half2 l = __halves2half2(__float2half_rn(rx), __float2half_rn(ry));
    hi = *(uint32_t*)&h;
    lo = *(uint32_t*)&l;
}
__device__ __forceinline__ uint32_t smem_u32(const void* p) {
    uint32_t a;
    asm("{ .reg .u64 t; cvta.to.shared.u64 t, %1; cvt.u32.u64 %0, t; }" : "=r"(a) : "l"(p));
    return a;
}
__device__ __forceinline__ void cp_async16(uint32_t dst, const void* src) {
    asm volatile("cp.async.cg.shared.global [%0], [%1], 16;" :: "r"(dst), "l"(src));
}

// ------------------------------------------------------------------
// Embedding gather (int32/int64 auto-detect)
// ------------------------------------------------------------------
__global__ __launch_bounds__(256) void embed_kernel(const int* __restrict__ idx32,
                                                    const float* __restrict__ wte,
                                                    float* __restrict__ x) {
    __shared__ int s_is64;
    if (threadIdx.x == 0) {
        int all0 = 1;
        #pragma unroll
        for (int i = 1; i < 16; i += 2)
            if (idx32[i] != 0) all0 = 0;
        s_is64 = all0;
    }
    __syncthreads();
    int gid = blockIdx.x * 256 + threadIdx.x;
    if (gid >= TOKENS * C_DIM) return;
    int t = gid / C_DIM;
    int c = gid - t * C_DIM;
    int id = s_is64 ? idx32[2 * t] : idx32[t];
    x[gid] = wte[id * C_DIM + c];
}

// ------------------------------------------------------------------
// f32 -> padded f16 conversion (wte / final x)
// ------------------------------------------------------------------
__global__ __launch_bounds__(256) void cvt_half_kernel(const float* __restrict__ src,
                                                       __half* __restrict__ dst,
                                                       int dstRows, int srcRows) {
    int idx = blockIdx.x * 256 + threadIdx.x;
    if (idx >= dstRows * 64) return;
    int r = idx >> 6, c4 = idx & 63;
    uint32_t p[2];
    if (c4 < 57 && r < srcRows) {
        float4 v = *(const float4*)&src[r * C_DIM + c4 * 4];
        p[0] = pack_h2(v.x, v.y);
        p[1] = pack_h2(v.z, v.w);
    } else {
        p[0] = 0u; p[1] = 0u;
    }
    *(uint2*)&dst[r * KPAD + c4 * 4] = *(uint2*)p;
}

// ------------------------------------------------------------------
// w_scan (all layers) -> transposed fp16 hi + lo, zero-padded.
// ------------------------------------------------------------------
__global__ __launch_bounds__(256) void cvt_wscan_kernel(const float* __restrict__ wsc,
                                                        __half* __restrict__ WhT,
                                                        __half* __restrict__ WlT) {
    int idx = blockIdx.x * 256 + threadIdx.x;
    if (idx >= NLAYER * WKP * 57) return;
    int L = idx / (WKP * 57);
    int rem = idx - L * (WKP * 57);
    int k = rem / 57, n4 = rem - (rem / 57) * 57;
    float4 v = make_float4(0.f, 0.f, 0.f, 0.f);
    if (k < C_DIM)
        v = *(const float4*)&wsc[L * C_DIM * C_DIM + k * C_DIM + n4 * 4];
    __half* wh = WhT + L * WNP * WKP;
    __half* wl = WlT + L * WNP * WKP;
    const float* vv = (const float*)&v;
    #pragma unroll
    for (int j = 0; j < 4; j++) {
        float x = vv[j];
        __half hi = __float2half_rn(x);
        __half lo = __float2half_rn(x - __half2float(hi));
        wh[(n4 * 4 + j) * WKP + k] = hi;
        wl[(n4 * 4 + j) * WKP + k] = lo;
    }
}

// ------------------------------------------------------------------
// LN stats only (float4 reads): mean + rstd per token
// ------------------------------------------------------------------
__global__ __launch_bounds__(256) void ln_stats_kernel(const float* __restrict__ x,
                                                       float2* __restrict__ stats) {
    int w = (blockIdx.x * 256 + threadIdx.x) >> 5;
    int lane = threadIdx.x & 31;
    if (w >= TOKENS) return;
    const float* row = x + w * C_DIM;
    float s = 0.f, s2 = 0.f;
    for (int c4 = lane; c4 < 57; c4 += 32) {
        float4 v = *(const float4*)&row[c4 * 4];
        s  += v.x + v.y + v.z + v.w;
        s2 += v.x * v.x + v.y * v.y + v.z * v.z + v.w * v.w;
    }
    #pragma unroll
    for (int o = 16; o > 0; o >>= 1) {
        s  += __shfl_xor_sync(0xffffffffu, s, o);
        s2 += __shfl_xor_sync(0xffffffffu, s2, o);
    }
    if (lane == 0) {
        float mean = s * (1.0f / C_DIM);
        float var = s2 * (1.0f / C_DIM) - mean * mean;
        stats[w] = make_float2(mean, rsqrtf(var + 1e-5f));
    }
}

// ------------------------------------------------------------------
// Split-fp16 internal GEMM (NT). AMODE 0 plain / 1 LN-fused / 2 A*A2.
// EPI 0 store / 1 += / 2 gelu. DUAL 1: grid.y doubled, second half
// uses B2/C2 (same M,N,K).
// ------------------------------------------------------------------
template<int AMODE, int EPI, int DUAL>
__global__ __launch_bounds__(256) void hgemm(
    const float* __restrict__ A, const float* __restrict__ A2,
    const float* __restrict__ B, float* __restrict__ Cc,
    int M, int N, int K,
    const float2* __restrict__ stats, const float* __restrict__ gamma,
    const float* __restrict__ B2, float* __restrict__ C2)
{
    __shared__ uint32_t Ah[64][20], Al[64][20], Bh[64][20], Bl[64][20];
    const int tid = threadIdx.x;
    const int lane = tid & 31, wid = tid >> 5;
    const int wm = wid >> 2, wn = wid & 3;
    const int l3 = lane & 3, lq = lane >> 2;
    const int m0 = blockIdx.x * 64;

    const float* Bp = B;
    float* Cp = Cc;
    int by = blockIdx.y;
    if (DUAL) {
        int ny = gridDim.y >> 1;
        if (by >= ny) { Bp = B2; Cp = C2; by -= ny; }
    }
    const int n0 = by * 64;

    float acc[2][2][4];
    #pragma unroll
    for (int i = 0; i < 2; i++)
        #pragma unroll
        for (int j = 0; j < 2; j++)
            #pragma unroll
            for (int q = 0; q < 4; q++) acc[i][j][q] = 0.f;

    const int nchunk = (K + 31) / 32;

    auto loadA = [&](int r, int k) -> float4 {
        float4 v = make_float4(0.f,0.f,0.f,0.f);
        if (k + 3 < K) {
            v = *(const float4*)&A[(m0 + r) * K + k];
            if (AMODE == 1) {
                float2 st = stats[m0 + r];
                float4 gg = *(const float4*)&gamma[k];
                v.x = (v.x - st.x) * st.y * gg.x;
                v.y = (v.y - st.x) * st.y * gg.y;
                v.z = (v.z - st.x) * st.y * gg.z;
                v.w = (v.w - st.x) * st.y * gg.w;
            }
            if (AMODE == 2) {
                float4 u = *(const float4*)&A2[(m0 + r) * K + k];
                v.x *= u.x; v.y *= u.y; v.z *= u.z; v.w *= u.w;
            }
        }
        return v;
    };

    float4 pa[2], pb[2];
    #pragma unroll
    for (int i = 0; i < 2; i++) {
        int idx = tid + i * 256;
        int r = idx >> 3, f = idx & 7;
        int k = f * 4;
        pa[i] = loadA(r, k);
        float4 v = make_float4(0.f,0.f,0.f,0.f);
        if (k + 3 < K && (n0 + r) < N)
            v = *(const float4*)&Bp[(n0 + r) * K + k];
        pb[i] = v;
    }

    for (int ch = 0; ch < nchunk; ch++) {
        __syncthreads();
        #pragma unroll
        for (int i = 0; i < 2; i++) {
            int idx = tid + i * 256;
            int r = idx >> 3, f = idx & 7;
            uint32_t h0, l0, h1, l1;
            split_h2(pa[i].x, pa[i].y, h0, l0);
            split_h2(pa[i].z, pa[i].w, h1, l1);
            Ah[r][f*2] = h0; Ah[r][f*2+1] = h1;
            Al[r][f*2] = l0; Al[r][f*2+1] = l1;
            split_h2(pb[i].x, pb[i].y, h0, l0);
            split_h2(pb[i].z, pb[i].w, h1, l1);
            Bh[r][f*2] = h0; Bh[r][f*2+1] = h1;
            Bl[r][f*2] = l0; Bl[r][f*2+1] = l1;
        }
        __syncthreads();
        if (ch + 1 < nchunk) {
            int k0 = (ch + 1) * 32;
            #pragma unroll
            for (int i = 0; i < 2; i++) {
                int idx = tid + i * 256;
                int r = idx >> 3, f = idx & 7;
                int k = k0 + f * 4;
                pa[i] = loadA(r, k);
                float4 v = make_float4(0.f,0.f,0.f,0.f);
                if (k + 3 < K && (n0 + r) < N)
                    v = *(const float4*)&Bp[(n0 + r) * K + k];
                pb[i] = v;
            }
        }
        #pragma unroll
        for (int kc2 = 0; kc2 < 16; kc2 += 8) {
            uint32_t ah[2][4], al[2][4], bh[2][2], bl[2][2];
            #pragma unroll
            for (int mt = 0; mt < 2; mt++) {
                int r = wm * 32 + mt * 16 + lq;
                ah[mt][0] = Ah[r    ][kc2 + l3];
                ah[mt][1] = Ah[r + 8][kc2 + l3];
                ah[mt][2] = Ah[r    ][kc2 + 4 + l3];
                ah[mt][3] = Ah[r + 8][kc2 + 4 + l3];
                al[mt][0] = Al[r    ][kc2 + l3];
                al[mt][1] = Al[r + 8][kc2 + l3];
                al[mt][2] = Al[r    ][kc2 + 4 + l3];
                al[mt][3] = Al[r + 8][kc2 + 4 + l3];
            }
            #pragma unroll
            for (int nt = 0; nt < 2; nt++) {
                int n = wn * 16 + nt * 8 + lq;
                bh[nt][0] = Bh[n][kc2 + l3];
                bh[nt][1] = Bh[n][kc2 + 4 + l3];
                bl[nt][0] = Bl[n][kc2 + l3];
                bl[nt][1] = Bl[n][kc2 + 4 + l3];
            }
            #pragma unroll
            for (int mt = 0; mt < 2; mt++)
                #pragma unroll
                for (int nt = 0; nt < 2; nt++) {
                    mma16(acc[mt][nt], ah[mt], bh[nt]);
                    mma16(acc[mt][nt], ah[mt], bl[nt]);
                    mma16(acc[mt][nt], al[mt], bh[nt]);
                }
        }
    }

    #pragma unroll
    for (int mt = 0; mt < 2; mt++) {
        #pragma unroll
        for (int nt = 0; nt < 2; nt++) {
            int n = n0 + wn * 16 + nt * 8 + l3 * 2;
            #pragma unroll
            for (int half = 0; half < 2; half++) {
                int mm = m0 + wm * 32 + mt * 16 + lq + half * 8;
                float r0 = acc[mt][nt][half * 2];
                float r1 = acc[mt][nt][half * 2 + 1];
                if (n < N) {
                    if (EPI == 1) r0 += Cp[mm * N + n];
                    if (EPI == 2) r0 = gelu_f(r0);
                    Cp[mm * N + n] = r0;
                }
                if (n + 1 < N) {
                    if (EPI == 1) r1 += Cp[mm * N + n + 1];
                    if (EPI == 2) r1 = gelu_f(r1);
                    Cp[mm * N + n + 1] = r1;
                }
            }
        }
    }
}

// ------------------------------------------------------------------
// Pipelined fp16 lm_head — R8-proven.
// ------------------------------------------------------------------
#define LMH_AW   (128 * 36)
#define LMH_SW   (2 * LMH_AW)
#define LMH_SMEM (2 * LMH_SW * 4)

__global__ __launch_bounds__(256) void lmhead_h2(
    const __half* __restrict__ Ah_g, const __half* __restrict__ Bh_g,
    float* __restrict__ C)
{
    extern __shared__ uint32_t dsm[];
    const uint32_t smem_base = smem_u32(dsm);

    const int tid = threadIdx.x;
    const int lane = tid & 31, wid = tid >> 5;
    const int wm = wid >> 2, wn = wid & 3;
    const int l3 = lane & 3, lq = lane >> 2;
    const int m0 = blockIdx.x * 128, n0 = blockIdx.y * 128;

    float acc[4][4][4];
    #pragma unroll
    for (int i = 0; i < 4; i++)
        #pragma unroll
        for (int j = 0; j < 4; j++)
            #pragma unroll
            for (int q = 0; q < 4; q++) acc[i][j][q] = 0.f;

    const int r_ld = tid >> 3;
    const int c16  = tid & 7;

    auto issue = [&](int kc, int bi) {
        uint32_t ab = smem_base + (uint32_t)bi * (LMH_SW * 4);
        uint32_t bb = ab + LMH_AW * 4;
        const __half* asrc = Ah_g + (size_t)(m0 + r_ld) * KPAD + kc * 64 + c16 * 8;
        const __half* bsrc = Bh_g + (size_t)(n0 + r_ld) * KPAD + kc * 64 + c16 * 8;
        #pragma unroll
        for (int i = 0; i < 4; i++) {
            int r = r_ld + i * 32;
            cp_async16(ab + (uint32_t)(r * 36 + c16 * 4) * 4,
                       asrc + (size_t)(i * 32) * KPAD);
            cp_async16(bb + (uint32_t)(r * 36 + c16 * 4) * 4,
                       bsrc + (size_t)(i * 32) * KPAD);
        }
        asm volatile("cp.async.commit_group;" ::: "memory");
    };

    issue(0, 0);

    #pragma unroll 1
    for (int kc = 0; kc < 4; kc++) {
        if (kc + 1 < 4) {
            issue(kc + 1, (kc + 1) & 1);
            asm volatile("cp.async.wait_group 1;" ::: "memory");
        } else {
            asm volatile("cp.async.wait_group 0;" ::: "memory");
        }
        __syncthreads();

        const uint32_t* As2 = dsm + (kc & 1) * LMH_SW;
        const uint32_t* Bs2 = As2 + LMH_AW;

        #pragma unroll
        for (int kc2 = 0; kc2 < 32; kc2 += 8) {
            uint32_t af[4][4], bf[4][2];
            #pragma unroll
            for (int mt = 0; mt < 4; mt++) {
                int r = wm * 64 + mt * 16 + lq;
                af[mt][0] = As2[r * 36 + kc2 + l3];
                af[mt][1] = As2[(r + 8) * 36 + kc2 + l3];
                af[mt][2] = As2[r * 36 + kc2 + 4 + l3];
                af[mt][3] = As2[(r + 8) * 36 + kc2 + 4 + l3];
            }
            #pragma unroll
            for (int nt = 0; nt < 4; nt++) {
                int n = wn * 32 + nt * 8 + lq;
                bf[nt][0] = Bs2[n * 36 + kc2 + l3];
                bf[nt][1] = Bs2[n * 36 + kc2 + 4 + l3];
            }
            #pragma unroll
            for (int mt = 0; mt < 4; mt++)
                #pragma unroll
                for (int nt = 0; nt < 4; nt++)
                    mma16(acc[mt][nt], af[mt], bf[nt]);
        }
        __syncthreads();
    }

    #pragma unroll
    for (int mt = 0; mt < 4; mt++) {
        #pragma unroll
        for (int nt = 0; nt < 4; nt++) {
            int n = n0 + wn * 32 + nt * 8 + l3 * 2;
            #pragma unroll
            for (int half = 0; half < 2; half++) {
                int mm = m0 + wm * 64 + mt * 16 + lq + half * 8;
                float* dst = &C[(size_t)mm * VOCAB + n];
                if (n     < VOCAB) dst[0] = acc[mt][nt][half * 2];
                if (n + 1 < VOCAB) dst[1] = acc[mt][nt][half * 2 + 1];
            }
        }
    }
}

// ------------------------------------------------------------------
// Grid-wide barrier (all 128 blocks resident)
// ------------------------------------------------------------------
__device__ __forceinline__ void grid_barrier() {
    __syncthreads();
    if (threadIdx.x == 0) {
        __threadfence();
        unsigned gen = atomicAdd(&g_bar_gen, 0u);
        unsigned t = atomicAdd(&g_bar_cnt, 1u);
        if (t == gridDim.x - 1) {
            atomicExch(&g_bar_cnt, 0u);
            __threadfence();
            atomicAdd(&g_bar_gen, 1u);
        } else {
            while (atomicAdd(&g_bar_gen, 0u) == gen) __nanosleep(64);
        }
    }
    __syncthreads();
}

// ------------------------------------------------------------------
// Persistent pscan v5: Wh RESIDENT in smem; Wl read DIRECTLY from
// global (L2/L1-resident, latency hidden by 16 warps). Full 3-term.
// 128 blocks x 512 threads, 16 tokens/block.
// smem words: mAh 16*124, mAl 16*124, rr 16*232, mx 16*232, Wh 232*124
//           = 160640 B
// ------------------------------------------------------------------
#define SCW_AW (16 * 124)
#define SCW_RR (16 * 232)
#define SCW_MX (16 * 232)
#define SCW_WH (232 * 124)
#define SCW_SMEM ((2*SCW_AW + SCW_RR + SCW_MX + SCW_WH) * 4)

__global__ __launch_bounds__(512) void scan_all_h(
    float* __restrict__ x0, float* __restrict__ x1,
    const __half* __restrict__ WhT, const __half* __restrict__ WlT,
    const float* __restrict__ ident)
{
    extern __shared__ uint32_t su[];
    uint32_t* mAh = su;
    uint32_t* mAl = mAh + SCW_AW;
    float*    rr  = (float*)(mAl + SCW_AW);
    float*    mx  = rr + SCW_RR;
    uint32_t* Wh  = (uint32_t*)(mx + SCW_MX);
    const uint32_t wh_base = smem_u32(Wh);
    __half* mAh_h = (__half*)mAh;
    __half* mAl_h = (__half*)mAl;

    const int tid = threadIdx.x;
    const int lane = tid & 31, wid = tid >> 5;   // wid 0..15
    const int l3 = lane & 3, lq = lane >> 2;
    const int T0 = blockIdx.x * 16;
    const int half_id = tid >> 8;
    const int hc = tid & 255;

    // ---- stage Wh (rows 0..231) ONCE, resident for all steps ----
    for (int i = tid; i < 232 * 30; i += 512) {
        int n = i / 30, s5 = i - (i / 30) * 30;
        cp_async16(wh_base + (uint32_t)(n * 124 + s5 * 4) * 4,
                   WhT + (size_t)n * WKP + s5 * 8);
    }
    asm volatile("cp.async.commit_group;" ::: "memory");
    asm volatile("cp.async.wait_group 0;" ::: "memory");
    __syncthreads();

    int step = 0;
    for (int off = 1; off < SEQ; off <<= 1, step++) {
        const float* xin = (step & 1) ? x1 : x0;
        float* xout      = (step & 1) ? x0 : x1;

        // ---- load + fp16 hi/lo split ----
        if (hc < 248) {
            int c = hc;
            #pragma unroll
            for (int tl = 0; tl < 8; tl++) {
                int t = half_id * 8 + tl;
                int tok = T0 + t;
                int tt = tok & (SEQ - 1);
                float rv = 0.f, lv = 0.f;
                if (c < C_DIM) {
                    rv = xin[tok * C_DIM + c];
                    lv = (tt >= off) ? xin[(tok - off) * C_DIM + c] : ident[c];
                }
                if (c < 232) rr[t * 232 + c] = rv;
                float s = lv + rv;
                __half hi = __float2half_rn(s);
                __half lo = __float2half_rn(s - __half2float(hi));
                mAh_h[t * 248 + c] = hi;
                mAl_h[t * 248 + c] = lo;
            }
        }
        __syncthreads();

        // ---- hi-MMA loop (Wh resident) ----
        float acc[2][4];
        #pragma unroll
        for (int i = 0; i < 2; i++)
            #pragma unroll
            for (int q = 0; q < 4; q++) acc[i][q] = 0.f;

        const bool ci1_ok = (wid < 13);   // n = 128+wid*8+lq < 232
        #pragma unroll
        for (int kk = 0; kk < 15; kk++) {
            uint32_t ah[4], al[4], bh[2];
            ah[0] = mAh[lq * 124 + kk * 8 + l3];
            ah[1] = mAh[(lq + 8) * 124 + kk * 8 + l3];
            ah[2] = mAh[lq * 124 + kk * 8 + 4 + l3];
            ah[3] = mAh[(lq + 8) * 124 + kk * 8 + 4 + l3];
            al[0] = mAl[lq * 124 + kk * 8 + l3];
            al[1] = mAl[(lq + 8) * 124 + kk * 8 + l3];
            al[2] = mAl[lq * 124 + kk * 8 + 4 + l3];
            al[3] = mAl[(lq + 8) * 124 + kk * 8 + 4 + l3];
            {
                int n = wid * 8 + lq;
                bh[0] = Wh[n * 124 + kk * 8 + l3];
                bh[1] = Wh[n * 124 + kk * 8 + 4 + l3];
                mma16(acc[0], ah, bh);
                mma16(acc[0], al, bh);
            }
            if (ci1_ok) {
                int n = 128 + wid * 8 + lq;
                bh[0] = Wh[n * 124 + kk * 8 + l3];
                bh[1] = Wh[n * 124 + kk * 8 + 4 + l3];
                mma16(acc[1], ah, bh);
                mma16(acc[1], al, bh);
            }
        }

        // ---- lo-MMA passes: Wl fragments straight from global ----
        {
            const int n0g = wid * 8 + lq;
            const __half* wl0 = WlT + (size_t)n0g * WKP;
            #pragma unroll
            for (int kk = 0; kk < 15; kk++) {
                uint32_t ah[4], bl[2];
                ah[0] = mAh[lq * 124 + kk * 8 + l3];
                ah[1] = mAh[(lq + 8) * 124 + kk * 8 + l3];
                ah[2] = mAh[lq * 124 + kk * 8 + 4 + l3];
                ah[3] = mAh[(lq + 8) * 124 + kk * 8 + 4 + l3];
                bl[0] = *(const uint32_t*)(wl0 + (kk * 8 + l3) * 2);
                bl[1] = *(const uint32_t*)(wl0 + (kk * 8 + 4 + l3) * 2);
                mma16(acc[0], ah, bl);
            }
            if (ci1_ok) {
                const __half* wl1 = WlT + (size_t)(128 + n0g) * WKP;
                #pragma unroll
                for (int kk = 0; kk < 15; kk++) {
                    uint32_t ah[4], bl[2];
                    ah[0] = mAh[lq * 124 + kk * 8 + l3];
                    ah[1] = mAh[(lq + 8) * 124 + kk * 8 + l3];
                    ah[2] = mAh[lq * 124 + kk * 8 + 4 + l3];
                    ah[3] = mAh[(lq + 8) * 124 + kk * 8 + 4 + l3];
                    bl[0] = *(const uint32_t*)(wl1 + (kk * 8 + l3) * 2);
                    bl[1] = *(const uint32_t*)(wl1 + (kk * 8 + 4 + l3) * 2);
                    mma16(acc[1], ah, bl);
                }
            }
        }

        // ---- store mix ----
        #pragma unroll
        for (int ci = 0; ci < 2; ci++) {
            int n = ci * 128 + wid * 8 + l3 * 2;
            if (n < C_DIM) {
                mx[lq * 232 + n]       = acc[ci][0];
                mx[(lq + 8) * 232 + n] = acc[ci][2];
            }
            if (n + 1 < C_DIM) {
                mx[lq * 232 + n + 1]       = acc[ci][1];
                mx[(lq + 8) * 232 + n + 1] = acc[ci][3];
            }
        }
        __syncthreads();

        // ---- combine: 64 (token,lane) pairs, 4 per warp ----
        const int d0 = lane;
        const int d1 = lane + 32;
        const bool has1 = (lane < HD - 32);
        #pragma unroll
        for (int e = 0; e < 4; e++) {
            int p = wid * 4 + e;
            int t = p >> 2;
            int l = p & 3;
            int tok = T0 + t;

            float s0 = __half2float(mAh_h[t * 248 + l * HD + d0])
                     + __half2float(mAl_h[t * 248 + l * HD + d0]);
            float q0 = s0 - rr[t * 232 + l * HD + d0];
            float q1 = 0.f;
            if (has1) {
                float s1 = __half2float(mAh_h[t * 248 + l * HD + d1])
                         + __half2float(mAl_h[t * 248 + l * HD + d1]);
                q1 = s1 - rr[t * 232 + l * HD + d1];
            }

            float sc[4];
            #pragma unroll
            for (int m = 0; m < 4; m++) {
                float pr = q0 * rr[t * 232 + m * HD + d0];
                if (has1) pr += q1 * rr[t * 232 + m * HD + d1];
                #pragma unroll
                for (int o = 16; o > 0; o >>= 1) pr += __shfl_xor_sync(0xffffffffu, pr, o);
                sc[m] = pr * 0.13245323570650439f;
            }
            float mxv = fmaxf(fmaxf(sc[0], sc[1]), fmaxf(sc[2], sc[3]));
            float e0 = expf(sc[0] - mxv), e1 = expf(sc[1] - mxv);
            float e2 = expf(sc[2] - mxv), e3 = expf(sc[3] - mxv);
            float inv = 1.0f / (e0 + e1 + e2 + e3);
            float a0 = e0 * inv, a1 = e1 * inv, a2 = e2 * inv, a3 = e3 * inv;

            float z0 = a0 * mx[t * 232 + 0 * HD + d0] + a1 * mx[t * 232 + 1 * HD + d0]
                     + a2 * mx[t * 232 + 2 * HD + d0] + a3 * mx[t * 232 + 3 * HD + d0];
            float z1 = 0.f;
            if (has1)
                z1 = a0 * mx[t * 232 + 0 * HD + d1] + a1 * mx[t * 232 + 1 * HD + d1]
                   + a2 * mx[t * 232 + 2 * HD + d1] + a3 * mx[t * 232 + 3 * HD + d1];

            float ss = z0 * z0 + z1 * z1;
            #pragma unroll
            for (int o = 16; o > 0; o >>= 1) ss += __shfl_xor_sync(0xffffffffu, ss, o);
            float scale = rsqrtf(ss * (1.0f / 57.0f) + 1e-6f) / (1.0f + (float)l);

            xout[tok * C_DIM + l * HD + d0] = q0 + z0 * scale;
            if (has1) xout[tok * C_DIM + l * HD + d1] = q1 + z1 * scale;
        }

        if ((off << 1) < SEQ) grid_barrier();
    }
}

// ------------------------------------------------------------------
extern "C" void kernel_launch(void* const* d_in, const int* in_sizes, int n_in,
                              void* d_out, int out_size) {
    const int*   idx    = (const int*)  d_in[0];
    const float* wte    = (const float*)d_in[1];
    const float* ln1_g  = (const float*)d_in[2];
    const float* ln2_g  = (const float*)d_in[3];
    const float* w_up   = (const float*)d_in[4];
    const float* w_v    = (const float*)d_in[5];
    const float* w_cpr  = (const float*)d_in[6];
    const float* w_scan = (const float*)d_in[7];
    const float* ident  = (const float*)d_in[8];
    const float* w_fc   = (const float*)d_in[9];
    const float* w_proj = (const float*)d_in[10];
    float* out = (float*)d_out;

    float *px, *pv, *pa, *pb, *pmlp;
    float2* pst;
    __half *pwh, *pxh, *pwsh, *pwsl;
    cudaGetSymbolAddress((void**)&px,   g_x);
    cudaGetSymbolAddress((void**)&pv,   g_v);
    cudaGetSymbolAddress((void**)&pa,   g_bufA);
    cudaGetSymbolAddress((void**)&pb,   g_bufB);
    cudaGetSymbolAddress((void**)&pmlp, g_mlp);
    cudaGetSymbolAddress((void**)&pst,  g_stats);
    cudaGetSymbolAddress((void**)&pwh,  g_wte_h);
    cudaGetSymbolAddress((void**)&pxh,  g_x_h);
    cudaGetSymbolAddress((void**)&pwsh, g_wsh);
    cudaGetSymbolAddress((void**)&pwsl, g_wsl);

    cudaFuncSetAttribute(scan_all_h,
                         cudaFuncAttributeMaxDynamicSharedMemorySize, SCW_SMEM);
    cudaFuncSetAttribute(lmhead_h2,
                         cudaFuncAttributeMaxDynamicSharedMemorySize, LMH_SMEM);

    const int CC = C_DIM * C_DIM;
    const int FC = FF * C_DIM;

    embed_kernel<<<(TOKENS * C_DIM + 255) / 256, 256>>>(idx, wte, px);
    cvt_half_kernel<<<(VPAD * 64 + 255) / 256, 256>>>(wte, pwh, VPAD, VOCAB);
    cvt_wscan_kernel<<<(NLAYER * WKP * 57 + 255) / 256, 256>>>(w_scan, pwsh, pwsl);

    for (int L = 0; L < NLAYER; L++) {
        const float* wupL  = w_up   + L * CC;
        const float* wvL   = w_v    + L * CC;
        const float* wcprL = w_cpr  + L * CC;
        const float* idL   = ident  + L * C_DIM;
        const float* wfcL  = w_fc   + L * FC;
        const float* wprL  = w_proj + L * FC;

        ln_stats_kernel<<<(TOKENS * 32 + 255) / 256, 256>>>(px, pst);

        // fused up+v: grid.y doubled, second half -> wv/pv
        dim3 gsd(TOKENS / 64, 2 * ((C_DIM + 63) / 64));
        hgemm<1,0,1><<<gsd, 256>>>(px, nullptr, wupL, pa, TOKENS, C_DIM, C_DIM,
                                   pst, ln1_g + L * C_DIM, wvL, pv);

        scan_all_h<<<TOKENS / 16, 512, SCW_SMEM>>>(
            pa, pb, pwsh + (size_t)L * WNP * WKP, pwsl + (size_t)L * WNP * WKP, idL);

        dim3 gs(TOKENS / 64, (C_DIM + 63) / 64);
        hgemm<2,1,0><<<gs, 256>>>(pa, pv, wcprL, px, TOKENS, C_DIM, C_DIM,
                                  nullptr, nullptr, nullptr, nullptr);

        ln_stats_kernel<<<(TOKENS * 32 + 255) / 256, 256>>>(px, pst);

        dim3 gf(TOKENS / 64, (FF + 63) / 64);
        hgemm<1,2,0><<<gf, 256>>>(px, nullptr, wfcL, pmlp, TOKENS, FF, C_DIM,
                                  pst, ln2_g + L * C_DIM, nullptr, nullptr);
        hgemm<0,1,0><<<gs, 256>>>(pmlp, nullptr, wprL, px, TOKENS, C_DIM, FF,
                                  nullptr, nullptr, nullptr, nullptr);
    }

    cvt_half_kernel<<<(TOKENS * 64 + 255) / 256, 256>>>(px, pxh, TOKENS, TOKENS);

    dim3 gl(TOKENS / 128, VPAD / 128);
    lmhead_h2<<<gl, 256, LMH_SMEM>>>(pxh, pwh, out);
}

// round 17
// speedup vs baseline: 1.0782x; 1.0203x over previous
#include <cuda_runtime.h>
#include <cuda_fp16.h>
#include <cstdint>
#include <math.h>

#define C_DIM 228
#define TOKENS 2048
#define SEQ 1024
#define HD 57
#define LANES 4
#define FF 912
#define NLAYER 4
#define VOCAB 50257
#define VPAD 50304
#define KPAD 256
#define WKP 240
#define WNP 256

// ------------------------------------------------------------------
// Scratch
// ------------------------------------------------------------------
__device__ float g_x   [TOKENS * C_DIM];
__device__ float g_v   [TOKENS * C_DIM];
__device__ float g_bufA[TOKENS * C_DIM];
__device__ float g_bufB[TOKENS * C_DIM];
__device__ float g_mlp [TOKENS * FF];
__device__ float2 g_stats[TOKENS];
__device__ __half g_wte_h[VPAD * KPAD];
__device__ __half g_x_h  [TOKENS * KPAD];
__device__ __half g_wsh  [NLAYER * WNP * WKP];
__device__ __half g_wsl  [NLAYER * WNP * WKP];
// pre-split internal weights (zero-init pads)
__device__ __half g_wup_h[NLAYER * 256 * 256], g_wup_l[NLAYER * 256 * 256];
__device__ __half g_wv_h [NLAYER * 256 * 256], g_wv_l [NLAYER * 256 * 256];
__device__ __half g_wcp_h[NLAYER * 256 * 256], g_wcp_l[NLAYER * 256 * 256];
__device__ __half g_wfc_h[NLAYER * 960 * 256], g_wfc_l[NLAYER * 960 * 256];
__device__ __half g_wpr_h[NLAYER * 256 * 928], g_wpr_l[NLAYER * 256 * 928];
__device__ unsigned g_bar_cnt = 0;
__device__ unsigned g_bar_gen = 0;

__device__ __forceinline__ float gelu_f(float x) {
    float x3 = x * x * x;
    return 0.5f * x * (1.0f + tanhf(0.7978845608028654f * (x + 0.044715f * x3)));
}
__device__ __forceinline__ void mma16(float* c, const uint32_t* a, const uint32_t* b) {
    asm volatile("mma.sync.aligned.m16n8k16.row.col.f32.f16.f16.f32 "
        "{%0,%1,%2,%3}, {%4,%5,%6,%7}, {%8,%9}, {%0,%1,%2,%3};"
        : "+f"(c[0]), "+f"(c[1]), "+f"(c[2]), "+f"(c[3])
        : "r"(a[0]), "r"(a[1]), "r"(a[2]), "r"(a[3]), "r"(b[0]), "r"(b[1]));
}
__device__ __forceinline__ uint32_t pack_h2(float x, float y) {
    __half2 h = __halves2half2(__float2half_rn(x), __float2half_rn(y));
    return *(uint32_t*)&h;
}
__device__ __forceinline__ void split_h2(float x, float y, uint32_t& hi, uint32_t& lo) {
    __half hx = __float2half_rn(x), hy = __float2half_rn(y);
    float rx = x - __half2float(hx), ry = y - __half2float(hy);
    __half2 h = __halves2half2(hx, hy);
    __half2 l = __halves2half2(__float2half_rn(rx), __float2half_rn(ry));
    hi = *(uint32_t*)&h;
    lo = *(uint32_t*)&l;
}
__device__ __forceinline__ uint32_t smem_u32(const void* p) {
    uint32_t a;
    asm("{ .reg .u64 t; cvta.to.shared.u64 t, %1; cvt.u32.u64 %0, t; }" : "=r"(a) : "l"(p));
    return a;
}
__device__ __forceinline__ void cp_async16(uint32_t dst, const void* src) {
    asm volatile("cp.async.cg.shared.global [%0], [%1], 16;" :: "r"(dst), "l"(src));
}

// ------------------------------------------------------------------
// Embedding gather (int32/int64 auto-detect)
// ------------------------------------------------------------------
__global__ __launch_bounds__(256) void embed_kernel(const int* __restrict__ idx32,
                                                    const float* __restrict__ wte,
                                                    float* __restrict__ x) {
    __shared__ int s_is64;
    if (threadIdx.x == 0) {
        int all0 = 1;
        #pragma unroll
        for (int i = 1; i < 16; i += 2)
            if (idx32[i] != 0) all0 = 0;
        s_is64 = all0;
    }
    __syncthreads();
    int gid = blockIdx.x * 256 + threadIdx.x;
    if (gid >= TOKENS * C_DIM) return;
    int t = gid / C_DIM;
    int c = gid - t * C_DIM;
    int id = s_is64 ? idx32[2 * t] : idx32[t];
    x[gid] = wte[id * C_DIM + c];
}

// ------------------------------------------------------------------
// f32 -> padded f16 conversion (wte / final x)
// ------------------------------------------------------------------
__global__ __launch_bounds__(256) void cvt_half_kernel(const float* __restrict__ src,
                                                       __half* __restrict__ dst,
                                                       int dstRows, int srcRows) {
    int idx = blockIdx.x * 256 + threadIdx.x;
    if (idx >= dstRows * 64) return;
    int r = idx >> 6, c4 = idx & 63;
    uint32_t p[2];
    if (c4 < 57 && r < srcRows) {
        float4 v = *(const float4*)&src[r * C_DIM + c4 * 4];
        p[0] = pack_h2(v.x, v.y);
        p[1] = pack_h2(v.z, v.w);
    } else {
        p[0] = 0u; p[1] = 0u;
    }
    *(uint2*)&dst[r * KPAD + c4 * 4] = *(uint2*)p;
}

// ------------------------------------------------------------------
// Generic weight pre-split: src fp32 [NLAYER][R][Ksrc] row-major
// -> dsth/dstl fp16 [NLAYER][RP][KP], zero-padded (globals zero-init).
// Ksrc % 4 == 0 assumed.
// ------------------------------------------------------------------
__global__ __launch_bounds__(256) void cvt_wsplit_kernel(
    const float* __restrict__ src, __half* __restrict__ dh, __half* __restrict__ dl,
    int R, int Ksrc, int KP, int RP, int total)
{
    int idx = blockIdx.x * 256 + threadIdx.x;
    if (idx >= total) return;
    int KP4 = KP >> 2;
    int L = idx / (R * KP4);
    int rem = idx - L * (R * KP4);
    int r = rem / KP4, c4 = rem - (rem / KP4) * KP4;
    int k = c4 * 4;
    float4 v = make_float4(0.f, 0.f, 0.f, 0.f);
    if (k < Ksrc)
        v = *(const float4*)&src[((size_t)L * R + r) * Ksrc + k];
    uint32_t h0, l0, h1, l1;
    split_h2(v.x, v.y, h0, l0);
    split_h2(v.z, v.w, h1, l1);
    size_t o = ((size_t)L * RP + r) * KP + k;
    uint32_t ph[2] = {h0, h1}, pl[2] = {l0, l1};
    *(uint2*)&dh[o] = *(uint2*)ph;
    *(uint2*)&dl[o] = *(uint2*)pl;
}

// ------------------------------------------------------------------
// w_scan (all layers) -> transposed fp16 hi + lo, zero-padded.
// ------------------------------------------------------------------
__global__ __launch_bounds__(256) void cvt_wscan_kernel(const float* __restrict__ wsc,
                                                        __half* __restrict__ WhT,
                                                        __half* __restrict__ WlT) {
    int idx = blockIdx.x * 256 + threadIdx.x;
    if (idx >= NLAYER * WKP * 57) return;
    int L = idx / (WKP * 57);
    int rem = idx - L * (WKP * 57);
    int k = rem / 57, n4 = rem - (rem / 57) * 57;
    float4 v = make_float4(0.f, 0.f, 0.f, 0.f);
    if (k < C_DIM)
        v = *(const float4*)&wsc[L * C_DIM * C_DIM + k * C_DIM + n4 * 4];
    __half* wh = WhT + L * WNP * WKP;
    __half* wl = WlT + L * WNP * WKP;
    const float* vv = (const float*)&v;
    #pragma unroll
    for (int j = 0; j < 4; j++) {
        float x = vv[j];
        __half hi = __float2half_rn(x);
        __half lo = __float2half_rn(x - __half2float(hi));
        wh[(n4 * 4 + j) * WKP + k] = hi;
        wl[(n4 * 4 + j) * WKP + k] = lo;
    }
}

// ------------------------------------------------------------------
// LN stats only (float4 reads): mean + rstd per token
// ------------------------------------------------------------------
__global__ __launch_bounds__(256) void ln_stats_kernel(const float* __restrict__ x,
                                                       float2* __restrict__ stats) {
    int w = (blockIdx.x * 256 + threadIdx.x) >> 5;
    int lane = threadIdx.x & 31;
    if (w >= TOKENS) return;
    const float* row = x + w * C_DIM;
    float s = 0.f, s2 = 0.f;
    for (int c4 = lane; c4 < 57; c4 += 32) {
        float4 v = *(const float4*)&row[c4 * 4];
        s  += v.x + v.y + v.z + v.w;
        s2 += v.x * v.x + v.y * v.y + v.z * v.z + v.w * v.w;
    }
    #pragma unroll
    for (int o = 16; o > 0; o >>= 1) {
        s  += __shfl_xor_sync(0xffffffffu, s, o);
        s2 += __shfl_xor_sync(0xffffffffu, s2, o);
    }
    if (lane == 0) {
        float mean = s * (1.0f / C_DIM);
        float var = s2 * (1.0f / C_DIM) - mean * mean;
        stats[w] = make_float2(mean, rsqrtf(var + 1e-5f));
    }
}

// ------------------------------------------------------------------
// Split-fp16 internal GEMM (NT), pre-split fp16 B via cp.async
// double-buffer. AMODE 0 plain / 1 LN-fused / 2 A*A2.
// EPI 0 store / 1 += / 2 gelu. DUAL 1: grid.y doubled, second half
// uses (Bh2,Bl2,C2). B buffers have row stride KP, rows padded.
// ------------------------------------------------------------------
template<int AMODE, int EPI, int DUAL>
__global__ __launch_bounds__(256) void hgemm(
    const float* __restrict__ A, const float* __restrict__ A2,
    const __half* __restrict__ Bh_g, const __half* __restrict__ Bl_g,
    float* __restrict__ Cc,
    int M, int N, int K, int KP,
    const float2* __restrict__ stats, const float* __restrict__ gamma,
    const __half* __restrict__ Bh2_g, const __half* __restrict__ Bl2_g,
    float* __restrict__ C2)
{
    __shared__ uint32_t Ah[64][20], Al[64][20];
    __shared__ uint32_t Bhs[2][64][20], Bls[2][64][20];
    const uint32_t bh_base = smem_u32(&Bhs[0][0][0]);
    const uint32_t bl_base = smem_u32(&Bls[0][0][0]);
    const int tid = threadIdx.x;
    const int lane = tid & 31, wid = tid >> 5;
    const int wm = wid >> 2, wn = wid & 3;
    const int l3 = lane & 3, lq = lane >> 2;
    const int m0 = blockIdx.x * 64;

    const __half* Bhp = Bh_g;
    const __half* Blp = Bl_g;
    float* Cp = Cc;
    int by = blockIdx.y;
    if (DUAL) {
        int ny = gridDim.y >> 1;
        if (by >= ny) { Bhp = Bh2_g; Blp = Bl2_g; Cp = C2; by -= ny; }
    }
    const int n0 = by * 64;

    float acc[2][2][4];
    #pragma unroll
    for (int i = 0; i < 2; i++)
        #pragma unroll
        for (int j = 0; j < 2; j++)
            #pragma unroll
            for (int q = 0; q < 4; q++) acc[i][j][q] = 0.f;

    const int nchunk = (K + 31) / 32;
    const int r_b = tid >> 2;      // 0..63
    const int c_b = tid & 3;       // 16B chunk slot (BK=32 halves = 4x16B)

    auto issueB = [&](int ch, int bi) {
        uint32_t off = (uint32_t)(bi * 64 * 20 + r_b * 20 + c_b * 4) * 4;
        cp_async16(bh_base + off, Bhp + (size_t)(n0 + r_b) * KP + ch * 32 + c_b * 8);
        cp_async16(bl_base + off, Blp + (size_t)(n0 + r_b) * KP + ch * 32 + c_b * 8);
        asm volatile("cp.async.commit_group;" ::: "memory");
    };

    auto loadA = [&](int r, int k) -> float4 {
        float4 v = make_float4(0.f,0.f,0.f,0.f);
        if (k + 3 < K) {
            v = *(const float4*)&A[(m0 + r) * K + k];
            if (AMODE == 1) {
                float2 st = stats[m0 + r];
                float4 gg = *(const float4*)&gamma[k];
                v.x = (v.x - st.x) * st.y * gg.x;
                v.y = (v.y - st.x) * st.y * gg.y;
                v.z = (v.z - st.x) * st.y * gg.z;
                v.w = (v.w - st.x) * st.y * gg.w;
            }
            if (AMODE == 2) {
                float4 u = *(const float4*)&A2[(m0 + r) * K + k];
                v.x *= u.x; v.y *= u.y; v.z *= u.z; v.w *= u.w;
            }
        }
        return v;
    };

    issueB(0, 0);
    float4 pa[2];
    #pragma unroll
    for (int i = 0; i < 2; i++) {
        int idx = tid + i * 256;
        int r = idx >> 3, f = idx & 7;
        pa[i] = loadA(r, f * 4);
    }

    for (int ch = 0; ch < nchunk; ch++) {
        __syncthreads();
        #pragma unroll
        for (int i = 0; i < 2; i++) {
            int idx = tid + i * 256;
            int r = idx >> 3, f = idx & 7;
            uint32_t h0, l0, h1, l1;
            split_h2(pa[i].x, pa[i].y, h0, l0);
            split_h2(pa[i].z, pa[i].w, h1, l1);
            Ah[r][f*2] = h0; Ah[r][f*2+1] = h1;
            Al[r][f*2] = l0; Al[r][f*2+1] = l1;
        }
        if (ch + 1 < nchunk) {
            issueB(ch + 1, (ch + 1) & 1);
            asm volatile("cp.async.wait_group 1;" ::: "memory");
        } else {
            asm volatile("cp.async.wait_group 0;" ::: "memory");
        }
        __syncthreads();
        if (ch + 1 < nchunk) {
            int k0 = (ch + 1) * 32;
            #pragma unroll
            for (int i = 0; i < 2; i++) {
                int idx = tid + i * 256;
                int r = idx >> 3, f = idx & 7;
                pa[i] = loadA(r, k0 + f * 4);
            }
        }
        const uint32_t (*Bh)[20] = Bhs[ch & 1];
        const uint32_t (*Bl)[20] = Bls[ch & 1];
        #pragma unroll
        for (int kc2 = 0; kc2 < 16; kc2 += 8) {
            uint32_t ah[2][4], al[2][4], bh[2][2], bl[2][2];
            #pragma unroll
            for (int mt = 0; mt < 2; mt++) {
                int r = wm * 32 + mt * 16 + lq;
                ah[mt][0] = Ah[r    ][kc2 + l3];
                ah[mt][1] = Ah[r + 8][kc2 + l3];
                ah[mt][2] = Ah[r    ][kc2 + 4 + l3];
                ah[mt][3] = Ah[r + 8][kc2 + 4 + l3];
                al[mt][0] = Al[r    ][kc2 + l3];
                al[mt][1] = Al[r + 8][kc2 + l3];
                al[mt][2] = Al[r    ][kc2 + 4 + l3];
                al[mt][3] = Al[r + 8][kc2 + 4 + l3];
            }
            #pragma unroll
            for (int nt = 0; nt < 2; nt++) {
                int n = wn * 16 + nt * 8 + lq;
                bh[nt][0] = Bh[n][kc2 + l3];
                bh[nt][1] = Bh[n][kc2 + 4 + l3];
                bl[nt][0] = Bl[n][kc2 + l3];
                bl[nt][1] = Bl[n][kc2 + 4 + l3];
            }
            #pragma unroll
            for (int mt = 0; mt < 2; mt++)
                #pragma unroll
                for (int nt = 0; nt < 2; nt++) {
                    mma16(acc[mt][nt], ah[mt], bh[nt]);
                    mma16(acc[mt][nt], ah[mt], bl[nt]);
                    mma16(acc[mt][nt], al[mt], bh[nt]);
                }
        }
    }

    #pragma unroll
    for (int mt = 0; mt < 2; mt++) {
        #pragma unroll
        for (int nt = 0; nt < 2; nt++) {
            int n = n0 + wn * 16 + nt * 8 + l3 * 2;
            #pragma unroll
            for (int half = 0; half < 2; half++) {
                int mm = m0 + wm * 32 + mt * 16 + lq + half * 8;
                float r0 = acc[mt][nt][half * 2];
                float r1 = acc[mt][nt][half * 2 + 1];
                if (n < N) {
                    if (EPI == 1) r0 += Cp[mm * N + n];
                    if (EPI == 2) r0 = gelu_f(r0);
                    Cp[mm * N + n] = r0;
                }
                if (n + 1 < N) {
                    if (EPI == 1) r1 += Cp[mm * N + n + 1];
                    if (EPI == 2) r1 = gelu_f(r1);
                    Cp[mm * N + n + 1] = r1;
                }
            }
        }
    }
}

// ------------------------------------------------------------------
// Pipelined fp16 lm_head — R8-proven.
// ------------------------------------------------------------------
#define LMH_AW   (128 * 36)
#define LMH_SW   (2 * LMH_AW)
#define LMH_SMEM (2 * LMH_SW * 4)

__global__ __launch_bounds__(256) void lmhead_h2(
    const __half* __restrict__ Ah_g, const __half* __restrict__ Bh_g,
    float* __restrict__ C)
{
    extern __shared__ uint32_t dsm[];
    const uint32_t smem_base = smem_u32(dsm);

    const int tid = threadIdx.x;
    const int lane = tid & 31, wid = tid >> 5;
    const int wm = wid >> 2, wn = wid & 3;
    const int l3 = lane & 3, lq = lane >> 2;
    const int m0 = blockIdx.x * 128, n0 = blockIdx.y * 128;

    float acc[4][4][4];
    #pragma unroll
    for (int i = 0; i < 4; i++)
        #pragma unroll
        for (int j = 0; j < 4; j++)
            #pragma unroll
            for (int q = 0; q < 4; q++) acc[i][j][q] = 0.f;

    const int r_ld = tid >> 3;
    const int c16  = tid & 7;

    auto issue = [&](int kc, int bi) {
        uint32_t ab = smem_base + (uint32_t)bi * (LMH_SW * 4);
        uint32_t bb = ab + LMH_AW * 4;
        const __half* asrc = Ah_g + (size_t)(m0 + r_ld) * KPAD + kc * 64 + c16 * 8;
        const __half* bsrc = Bh_g + (size_t)(n0 + r_ld) * KPAD + kc * 64 + c16 * 8;
        #pragma unroll
        for (int i = 0; i < 4; i++) {
            int r = r_ld + i * 32;
            cp_async16(ab + (uint32_t)(r * 36 + c16 * 4) * 4,
                       asrc + (size_t)(i * 32) * KPAD);
            cp_async16(bb + (uint32_t)(r * 36 + c16 * 4) * 4,
                       bsrc + (size_t)(i * 32) * KPAD);
        }
        asm volatile("cp.async.commit_group;" ::: "memory");
    };

    issue(0, 0);

    #pragma unroll 1
    for (int kc = 0; kc < 4; kc++) {
        if (kc + 1 < 4) {
            issue(kc + 1, (kc + 1) & 1);
            asm volatile("cp.async.wait_group 1;" ::: "memory");
        } else {
            asm volatile("cp.async.wait_group 0;" ::: "memory");
        }
        __syncthreads();

        const uint32_t* As2 = dsm + (kc & 1) * LMH_SW;
        const uint32_t* Bs2 = As2 + LMH_AW;

        #pragma unroll
        for (int kc2 = 0; kc2 < 32; kc2 += 8) {
            uint32_t af[4][4], bf[4][2];
            #pragma unroll
            for (int mt = 0; mt < 4; mt++) {
                int r = wm * 64 + mt * 16 + lq;
                af[mt][0] = As2[r * 36 + kc2 + l3];
                af[mt][1] = As2[(r + 8) * 36 + kc2 + l3];
                af[mt][2] = As2[r * 36 + kc2 + 4 + l3];
                af[mt][3] = As2[(r + 8) * 36 + kc2 + 4 + l3];
            }
            #pragma unroll
            for (int nt = 0; nt < 4; nt++) {
                int n = wn * 32 + nt * 8 + lq;
                bf[nt][0] = Bs2[n * 36 + kc2 + l3];
                bf[nt][1] = Bs2[n * 36 + kc2 + 4 + l3];
            }
            #pragma unroll
            for (int mt = 0; mt < 4; mt++)
                #pragma unroll
                for (int nt = 0; nt < 4; nt++)
                    mma16(acc[mt][nt], af[mt], bf[nt]);
        }
        __syncthreads();
    }

    #pragma unroll
    for (int mt = 0; mt < 4; mt++) {
        #pragma unroll
        for (int nt = 0; nt < 4; nt++) {
            int n = n0 + wn * 32 + nt * 8 + l3 * 2;
            #pragma unroll
            for (int half = 0; half < 2; half++) {
                int mm = m0 + wm * 64 + mt * 16 + lq + half * 8;
                float* dst = &C[(size_t)mm * VOCAB + n];
                if (n     < VOCAB) dst[0] = acc[mt][nt][half * 2];
                if (n + 1 < VOCAB) dst[1] = acc[mt][nt][half * 2 + 1];
            }
        }
    }
}

// ------------------------------------------------------------------
// Grid-wide barrier (all 128 blocks resident)
// ------------------------------------------------------------------
__device__ __forceinline__ void grid_barrier() {
    __syncthreads();
    if (threadIdx.x == 0) {
        __threadfence();
        unsigned gen = atomicAdd(&g_bar_gen, 0u);
        unsigned t = atomicAdd(&g_bar_cnt, 1u);
        if (t == gridDim.x - 1) {
            atomicExch(&g_bar_cnt, 0u);
            __threadfence();
            atomicAdd(&g_bar_gen, 1u);
        } else {
            while (atomicAdd(&g_bar_gen, 0u) == gen) __nanosleep(64);
        }
    }
    __syncthreads();
}

// ------------------------------------------------------------------
// Persistent pscan v6: Wh resident, Wl from global, lo-MMAs
// interleaved into the hi loop. Full 3-term.
// 128 blocks x 512 threads, 16 tokens/block.
// ------------------------------------------------------------------
#define SCW_AW (16 * 124)
#define SCW_RR (16 * 232)
#define SCW_MX (16 * 232)
#define SCW_WH (232 * 124)
#define SCW_SMEM ((2*SCW_AW + SCW_RR + SCW_MX + SCW_WH) * 4)

__global__ __launch_bounds__(512) void scan_all_h(
    float* __restrict__ x0, float* __restrict__ x1,
    const __half* __restrict__ WhT, const __half* __restrict__ WlT,
    const float* __restrict__ ident)
{
    extern __shared__ uint32_t su[];
    uint32_t* mAh = su;
    uint32_t* mAl = mAh + SCW_AW;
    float*    rr  = (float*)(mAl + SCW_AW);
    float*    mx  = rr + SCW_RR;
    uint32_t* Wh  = (uint32_t*)(mx + SCW_MX);
    const uint32_t wh_base = smem_u32(Wh);
    __half* mAh_h = (__half*)mAh;
    __half* mAl_h = (__half*)mAl;

    const int tid = threadIdx.x;
    const int lane = tid & 31, wid = tid >> 5;
    const int l3 = lane & 3, lq = lane >> 2;
    const int T0 = blockIdx.x * 16;
    const int half_id = tid >> 8;
    const int hc = tid & 255;

    for (int i = tid; i < 232 * 30; i += 512) {
        int n = i / 30, s5 = i - (i / 30) * 30;
        cp_async16(wh_base + (uint32_t)(n * 124 + s5 * 4) * 4,
                   WhT + (size_t)n * WKP + s5 * 8);
    }
    asm volatile("cp.async.commit_group;" ::: "memory");
    asm volatile("cp.async.wait_group 0;" ::: "memory");
    __syncthreads();

    int step = 0;
    for (int off = 1; off < SEQ; off <<= 1, step++) {
        const float* xin = (step & 1) ? x1 : x0;
        float* xout      = (step & 1) ? x0 : x1;

        if (hc < 248) {
            int c = hc;
            #pragma unroll
            for (int tl = 0; tl < 8; tl++) {
                int t = half_id * 8 + tl;
                int tok = T0 + t;
                int tt = tok & (SEQ - 1);
                float rv = 0.f, lv = 0.f;
                if (c < C_DIM) {
                    rv = xin[tok * C_DIM + c];
                    lv = (tt >= off) ? xin[(tok - off) * C_DIM + c] : ident[c];
                }
                if (c < 232) rr[t * 232 + c] = rv;
                float s = lv + rv;
                __half hi = __float2half_rn(s);
                __half lo = __float2half_rn(s - __half2float(hi));
                mAh_h[t * 248 + c] = hi;
                mAl_h[t * 248 + c] = lo;
            }
        }
        __syncthreads();

        // ---- mix GEMM: hi from resident Wh, lo from global Wl, fused ----
        float acc[2][4];
        #pragma unroll
        for (int i = 0; i < 2; i++)
            #pragma unroll
            for (int q = 0; q < 4; q++) acc[i][q] = 0.f;

        const bool ci1_ok = (wid < 13);
        const int n0g = wid * 8 + lq;
        const __half* wl0 = WlT + (size_t)n0g * WKP;
        const __half* wl1 = WlT + (size_t)(128 + n0g) * WKP;
        #pragma unroll
        for (int kk = 0; kk < 15; kk++) {
            uint32_t ah[4], al[4], bh[2], bl[2];
            ah[0] = mAh[lq * 124 + kk * 8 + l3];
            ah[1] = mAh[(lq + 8) * 124 + kk * 8 + l3];
            ah[2] = mAh[lq * 124 + kk * 8 + 4 + l3];
            ah[3] = mAh[(lq + 8) * 124 + kk * 8 + 4 + l3];
            al[0] = mAl[lq * 124 + kk * 8 + l3];
            al[1] = mAl[(lq + 8) * 124 + kk * 8 + l3];
            al[2] = mAl[lq * 124 + kk * 8 + 4 + l3];
            al[3] = mAl[(lq + 8) * 124 + kk * 8 + 4 + l3];
            {
                int n = wid * 8 + lq;
                bh[0] = Wh[n * 124 + kk * 8 + l3];
                bh[1] = Wh[n * 124 + kk * 8 + 4 + l3];
                bl[0] = *(const uint32_t*)(wl0 + (kk * 8 + l3) * 2);
                bl[1] = *(const uint32_t*)(wl0 + (kk * 8 + 4 + l3) * 2);
                mma16(acc[0], ah, bh);
                mma16(acc[0], al, bh);
                mma16(acc[0], ah, bl);
            }
            if (ci1_ok) {
                int n = 128 + wid * 8 + lq;
                bh[0] = Wh[n * 124 + kk * 8 + l3];
                bh[1] = Wh[n * 124 + kk * 8 + 4 + l3];
                bl[0] = *(const uint32_t*)(wl1 + (kk * 8 + l3) * 2);
                bl[1] = *(const uint32_t*)(wl1 + (kk * 8 + 4 + l3) * 2);
                mma16(acc[1], ah, bh);
                mma16(acc[1], al, bh);
                mma16(acc[1], ah, bl);
            }
        }

        #pragma unroll
        for (int ci = 0; ci < 2; ci++) {
            int n = ci * 128 + wid * 8 + l3 * 2;
            if (n < C_DIM) {
                mx[lq * 232 + n]       = acc[ci][0];
                mx[(lq + 8) * 232 + n] = acc[ci][2];
            }
            if (n + 1 < C_DIM) {
                mx[lq * 232 + n + 1]       = acc[ci][1];
                mx[(lq + 8) * 232 + n + 1] = acc[ci][3];
            }
        }
        __syncthreads();

        // ---- combine ----
        const int d0 = lane;
        const int d1 = lane + 32;
        const bool has1 = (lane < HD - 32);
        #pragma unroll
        for (int e = 0; e < 4; e++) {
            int p = wid * 4 + e;
            int t = p >> 2;
            int l = p & 3;
            int tok = T0 + t;

            float s0 = __half2float(mAh_h[t * 248 + l * HD + d0])
                     + __half2float(mAl_h[t * 248 + l * HD + d0]);
            float q0 = s0 - rr[t * 232 + l * HD + d0];
            float q1 = 0.f;
            if (has1) {
                float s1 = __half2float(mAh_h[t * 248 + l * HD + d1])
                         + __half2float(mAl_h[t * 248 + l * HD + d1]);
                q1 = s1 - rr[t * 232 + l * HD + d1];
            }

            float sc[4];
            #pragma unroll
            for (int m = 0; m < 4; m++) {
                float pr = q0 * rr[t * 232 + m * HD + d0];
                if (has1) pr += q1 * rr[t * 232 + m * HD + d1];
                #pragma unroll
                for (int o = 16; o > 0; o >>= 1) pr += __shfl_xor_sync(0xffffffffu, pr, o);
                sc[m] = pr * 0.13245323570650439f;
            }
            float mxv = fmaxf(fmaxf(sc[0], sc[1]), fmaxf(sc[2], sc[3]));
            float e0 = expf(sc[0] - mxv), e1 = expf(sc[1] - mxv);
            float e2 = expf(sc[2] - mxv), e3 = expf(sc[3] - mxv);
            float inv = 1.0f / (e0 + e1 + e2 + e3);
            float a0 = e0 * inv, a1 = e1 * inv, a2 = e2 * inv, a3 = e3 * inv;

            float z0 = a0 * mx[t * 232 + 0 * HD + d0] + a1 * mx[t * 232 + 1 * HD + d0]
                     + a2 * mx[t * 232 + 2 * HD + d0] + a3 * mx[t * 232 + 3 * HD + d0];
            float z1 = 0.f;
            if (has1)
                z1 = a0 * mx[t * 232 + 0 * HD + d1] + a1 * mx[t * 232 + 1 * HD + d1]
                   + a2 * mx[t * 232 + 2 * HD + d1] + a3 * mx[t * 232 + 3 * HD + d1];

            float ss = z0 * z0 + z1 * z1;
            #pragma unroll
            for (int o = 16; o > 0; o >>= 1) ss += __shfl_xor_sync(0xffffffffu, ss, o);
            float scale = rsqrtf(ss * (1.0f / 57.0f) + 1e-6f) / (1.0f + (float)l);

            xout[tok * C_DIM + l * HD + d0] = q0 + z0 * scale;
            if (has1) xout[tok * C_DIM + l * HD + d1] = q1 + z1 * scale;
        }

        if ((off << 1) < SEQ) grid_barrier();
    }
}

// ------------------------------------------------------------------
extern "C" void kernel_launch(void* const* d_in, const int* in_sizes, int n_in,
                              void* d_out, int out_size) {
    const int*   idx    = (const int*)  d_in[0];
    const float* wte    = (const float*)d_in[1];
    const float* ln1_g  = (const float*)d_in[2];
    const float* ln2_g  = (const float*)d_in[3];
    const float* w_up   = (const float*)d_in[4];
    const float* w_v    = (const float*)d_in[5];
    const float* w_cpr  = (const float*)d_in[6];
    const float* w_scan = (const float*)d_in[7];
    const float* ident  = (const float*)d_in[8];
    const float* w_fc   = (const float*)d_in[9];
    const float* w_proj = (const float*)d_in[10];
    float* out = (float*)d_out;

    float *px, *pv, *pa, *pb, *pmlp;
    float2* pst;
    __half *pwh, *pxh, *pwsh, *pwsl;
    __half *upH, *upL, *vH, *vL, *cpH, *cpL, *fcH, *fcL, *prH, *prL;
    cudaGetSymbolAddress((void**)&px,   g_x);
    cudaGetSymbolAddress((void**)&pv,   g_v);
    cudaGetSymbolAddress((void**)&pa,   g_bufA);
    cudaGetSymbolAddress((void**)&pb,   g_bufB);
    cudaGetSymbolAddress((void**)&pmlp, g_mlp);
    cudaGetSymbolAddress((void**)&pst,  g_stats);
    cudaGetSymbolAddress((void**)&pwh,  g_wte_h);
    cudaGetSymbolAddress((void**)&pxh,  g_x_h);
    cudaGetSymbolAddress((void**)&pwsh, g_wsh);
    cudaGetSymbolAddress((void**)&pwsl, g_wsl);
    cudaGetSymbolAddress((void**)&upH, g_wup_h); cudaGetSymbolAddress((void**)&upL, g_wup_l);
    cudaGetSymbolAddress((void**)&vH,  g_wv_h);  cudaGetSymbolAddress((void**)&vL,  g_wv_l);
    cudaGetSymbolAddress((void**)&cpH, g_wcp_h); cudaGetSymbolAddress((void**)&cpL, g_wcp_l);
    cudaGetSymbolAddress((void**)&fcH, g_wfc_h); cudaGetSymbolAddress((void**)&fcL, g_wfc_l);
    cudaGetSymbolAddress((void**)&prH, g_wpr_h); cudaGetSymbolAddress((void**)&prL, g_wpr_l);

    cudaFuncSetAttribute(scan_all_h,
                         cudaFuncAttributeMaxDynamicSharedMemorySize, SCW_SMEM);
    cudaFuncSetAttribute(lmhead_h2,
                         cudaFuncAttributeMaxDynamicSharedMemorySize, LMH_SMEM);

    embed_kernel<<<(TOKENS * C_DIM + 255) / 256, 256>>>(idx, wte, px);
    cvt_half_kernel<<<(VPAD * 64 + 255) / 256, 256>>>(wte, pwh, VPAD, VOCAB);
    cvt_wscan_kernel<<<(NLAYER * WKP * 57 + 255) / 256, 256>>>(w_scan, pwsh, pwsl);
    {
        int t1 = NLAYER * 228 * 64;   // R=228, KP=256
        cvt_wsplit_kernel<<<(t1 + 255) / 256, 256>>>(w_up,  upH, upL, 228, 228, 256, 256, t1);
        cvt_wsplit_kernel<<<(t1 + 255) / 256, 256>>>(w_v,   vH,  vL,  228, 228, 256, 256, t1);
        cvt_wsplit_kernel<<<(t1 + 255) / 256, 256>>>(w_cpr, cpH, cpL, 228, 228, 256, 256, t1);
        int t2 = NLAYER * 912 * 64;   // R=912, KP=256
        cvt_wsplit_kernel<<<(t2 + 255) / 256, 256>>>(w_fc,  fcH, fcL, 912, 228, 256, 960, t2);
        int t3 = NLAYER * 228 * 232;  // R=228, KP=928
        cvt_wsplit_kernel<<<(t3 + 255) / 256, 256>>>(w_proj, prH, prL, 228, 912, 928, 256, t3);
    }

    for (int L = 0; L < NLAYER; L++) {
        size_t o1 = (size_t)L * 256 * 256;
        size_t o2 = (size_t)L * 960 * 256;
        size_t o3 = (size_t)L * 256 * 928;
        const float* idL = ident + L * C_DIM;

        ln_stats_kernel<<<(TOKENS * 32 + 255) / 256, 256>>>(px, pst);

        dim3 gsd(TOKENS / 64, 2 * ((C_DIM + 63) / 64));
        hgemm<1,0,1><<<gsd, 256>>>(px, nullptr, upH + o1, upL + o1, pa,
                                   TOKENS, C_DIM, C_DIM, 256,
                                   pst, ln1_g + L * C_DIM, vH + o1, vL + o1, pv);

        scan_all_h<<<TOKENS / 16, 512, SCW_SMEM>>>(
            pa, pb, pwsh + (size_t)L * WNP * WKP, pwsl + (size_t)L * WNP * WKP, idL);

        dim3 gs(TOKENS / 64, (C_DIM + 63) / 64);
        hgemm<2,1,0><<<gs, 256>>>(pa, pv, cpH + o1, cpL + o1, px,
                                  TOKENS, C_DIM, C_DIM, 256,
                                  nullptr, nullptr, nullptr, nullptr, nullptr);

        ln_stats_kernel<<<(TOKENS * 32 + 255) / 256, 256>>>(px, pst);

        dim3 gf(TOKENS / 64, (FF + 63) / 64);
        hgemm<1,2,0><<<gf, 256>>>(px, nullptr, fcH + o2, fcL + o2, pmlp,
                                  TOKENS, FF, C_DIM, 256,
                                  pst, ln2_g + L * C_DIM, nullptr, nullptr, nullptr);
        hgemm<0,1,0><<<gs, 256>>>(pmlp, nullptr, prH + o3, prL + o3, px,
                                  TOKENS, C_DIM, FF, 928,
                                  nullptr, nullptr, nullptr, nullptr, nullptr);
    }

    cvt_half_kernel<<<(TOKENS * 64 + 255) / 256, 256>>>(px, pxh, TOKENS, TOKENS);

    dim3 gl(TOKENS / 128, VPAD / 128);
    lmhead_h2<<<gl, 256, LMH_SMEM>>>(pxh, pwh, out);
}